// round 9
// baseline (speedup 1.0000x reference)
#include <cuda_runtime.h>
#include <cuda_bf16.h>
#include <cuda_fp16.h>
#include <math.h>
#include <stdint.h>

// ---------------------------------------------------------------------------
// ResGCN15 (sm_103 -> HMMA mma.sync, bf16 hi/lo split fp32 emulation).
// Fused mid-layer (agg(x@W)==agg(x)@W): gather(scaled-f16 slab) -> smem A ->
// GEMM -> relu+bias+residual epilogue -> hist hi/lo + next f16 slab.
// Activation slabs scaled 2^-15 (activations ~8x larger than sup; 2^-10
// overflowed fp16 -> R8 NaN). Final GEMM reads f16 slabs, W15 f16 hi/lo.
// ---------------------------------------------------------------------------

#define MAX_N 50000
#define MAX_E 800000
#define NHID 128
#define NCLASS 40
#define LDK 40          // smem row stride for 32-elem K-chunk tiles (+8 pad)
#define LDA 136         // smem row stride for full-128-col A tiles (17*16B)

#define SUP_SCALE    0.0009765625f     // 2^-10 (layer-1 sup = x@W1)
#define SUP_UNSCALE  1024.0f
#define SLAB_SCALE   0.000030517578125f // 2^-15 (activation history slabs)
#define SLAB_UNSCALE 32768.0f

#define WOFF_W0   0
#define WOFF_W1   32768
#define WOFF_MID  65536
#define WOFF_W15  278528
#define WT_TOTAL  364544
#define W15_E     (48 * 1792)

__device__ __align__(16) int   g_deg[MAX_N];
__device__ __align__(16) int   g_offs[MAX_N + 1];
__device__ __align__(16) int   g_cursor[MAX_N];
__device__ __align__(16) int   g_csr_src[MAX_E];
__device__ __align__(16) float g_csr_w[MAX_E];
__device__ __align__(16) float g_z[(size_t)MAX_N * NHID];
__device__ __align__(16) __half g_sup[(size_t)MAX_N * NHID];
__device__ __align__(16) float g_acc[(size_t)MAX_N * NCLASS];
__device__ __align__(16) __nv_bfloat16 g_wthi[WT_TOTAL];
__device__ __align__(16) __nv_bfloat16 g_wtlo[WT_TOTAL];
__device__ __align__(16) __half g_w15fh[W15_E];
__device__ __align__(16) __half g_w15fl[W15_E];
__device__ __align__(16) __nv_bfloat16 g_xhi[(size_t)MAX_N * 256];
__device__ __align__(16) __nv_bfloat16 g_xlo[(size_t)MAX_N * 256];
__device__ __align__(16) __nv_bfloat16 g_hhi[(size_t)14 * MAX_N * NHID];
__device__ __align__(16) __nv_bfloat16 g_hlo[(size_t)14 * MAX_N * NHID];
__device__ __align__(16) __half g_hf16[(size_t)14 * MAX_N * NHID];   // scaled 2^-15

// ---------------------------------------------------------------------------
// helpers
// ---------------------------------------------------------------------------
__device__ __forceinline__ uint32_t s2u(const void* p) {
    return (uint32_t)__cvta_generic_to_shared(p);
}
__device__ __forceinline__ void ldsm4(uint32_t* r, uint32_t addr) {
    asm volatile("ldmatrix.sync.aligned.m8n8.x4.shared.b16 {%0,%1,%2,%3}, [%4];"
                 : "=r"(r[0]), "=r"(r[1]), "=r"(r[2]), "=r"(r[3]) : "r"(addr));
}
__device__ __forceinline__ void mma_bf16(float* d, const uint32_t* a,
                                         uint32_t b0, uint32_t b1) {
    asm volatile(
        "mma.sync.aligned.m16n8k16.row.col.f32.bf16.bf16.f32 "
        "{%0,%1,%2,%3}, {%4,%5,%6,%7}, {%8,%9}, {%0,%1,%2,%3};"
        : "+f"(d[0]), "+f"(d[1]), "+f"(d[2]), "+f"(d[3])
        : "r"(a[0]), "r"(a[1]), "r"(a[2]), "r"(a[3]), "r"(b0), "r"(b1));
}
__device__ __forceinline__ void mma_fp16(float* d, const uint32_t* a,
                                         uint32_t b0, uint32_t b1) {
    asm volatile(
        "mma.sync.aligned.m16n8k16.row.col.f32.f16.f16.f32 "
        "{%0,%1,%2,%3}, {%4,%5,%6,%7}, {%8,%9}, {%0,%1,%2,%3};"
        : "+f"(d[0]), "+f"(d[1]), "+f"(d[2]), "+f"(d[3])
        : "r"(a[0]), "r"(a[1]), "r"(a[2]), "r"(a[3]), "r"(b0), "r"(b1));
}
__device__ __forceinline__ void split1(float v, __nv_bfloat16& h, __nv_bfloat16& l) {
    h = __float2bfloat16(v);
    l = __float2bfloat16(v - __bfloat162float(h));
}
__device__ __forceinline__ float2 unpack2(uint32_t u) {
    __nv_bfloat162 b;
    *reinterpret_cast<uint32_t*>(&b) = u;
    return __bfloat1622float2(b);
}
__device__ __forceinline__ void cp16(uint32_t saddr, const void* gptr, uint32_t sz) {
    asm volatile("cp.async.cg.shared.global [%0], [%1], 16, %2;"
                 :: "r"(saddr), "l"(gptr), "r"(sz));
}
#define CP_COMMIT() asm volatile("cp.async.commit_group;")

// ---------------------------------------------------------------------------
// CSR build
// ---------------------------------------------------------------------------
__global__ void zero_deg_kernel(int n) {
    int i = blockIdx.x * blockDim.x + threadIdx.x;
    if (i < n) g_deg[i] = 0;
}
__global__ void hist_kernel(const int* __restrict__ dst, int E) {
    int i = blockIdx.x * blockDim.x + threadIdx.x;
    if (i < E) atomicAdd(&g_deg[dst[i]], 1);
}
__global__ void scan_kernel(int n) {
    __shared__ int sums[1024];
    const int t = threadIdx.x;
    const int chunk = (n + 1023) >> 10;
    const int begin = t * chunk;
    const int end = min(begin + chunk, n);
    int s = 0;
    for (int i = begin; i < end; i++) s += g_deg[i];
    sums[t] = s;
    __syncthreads();
    for (int d = 1; d < 1024; d <<= 1) {
        int v = (t >= d) ? sums[t - d] : 0;
        __syncthreads();
        sums[t] += v;
        __syncthreads();
    }
    int run = (t == 0) ? 0 : sums[t - 1];
    if (t == 0) g_offs[0] = 0;
    for (int i = begin; i < end; i++) {
        g_cursor[i] = run;
        run += g_deg[i];
        g_offs[i + 1] = run;
    }
}
__global__ void scatter_kernel(const int* __restrict__ src, const int* __restrict__ dst,
                               const float* __restrict__ w, int E) {
    int i = blockIdx.x * blockDim.x + threadIdx.x;
    if (i < E) {
        int d = dst[i];
        int pos = atomicAdd(&g_cursor[d], 1);
        g_csr_src[pos] = src[i];
        g_csr_w[pos] = w[i];
    }
}

// ---------------------------------------------------------------------------
// prep: weights transposed + split; W15 additionally split to f16 hi/lo
// ---------------------------------------------------------------------------
__global__ void split_w_kernel(const float* __restrict__ W0, const float* __restrict__ W1,
                               const float* __restrict__ Wmid, const float* __restrict__ W15) {
    int i = blockIdx.x * blockDim.x + threadIdx.x;
    if (i >= WT_TOTAL) return;
    float v;
    if (i < 32768) {
        int n = i >> 8, k = i & 255;
        v = W0[k * 128 + n];
    } else if (i < 65536) {
        int j = i - 32768;
        int n = j >> 8, k = j & 255;
        v = W1[k * 128 + n];
    } else if (i < 278528) {
        int j = i - 65536;
        int l = j >> 14, jj = j & 16383;
        int n = jj >> 7, k = jj & 127;
        v = Wmid[l * 16384 + k * 128 + n];
    } else {
        int j = i - 278528;
        int n = j / 1792, k = j % 1792;
        v = (n < 40) ? W15[(size_t)k * 40 + n] : 0.f;
        __half fh = __float2half_rn(v);
        __half fl = __float2half_rn(v - __half2float(fh));
        g_w15fh[j] = fh;
        g_w15fl[j] = fl;
    }
    __nv_bfloat16 h, l;
    split1(v, h, l);
    g_wthi[i] = h;
    g_wtlo[i] = l;
}
__global__ void split_x_kernel(const float* __restrict__ x, int total) {
    int i = blockIdx.x * blockDim.x + threadIdx.x;
    if (i >= total) return;
    __nv_bfloat16 h, l;
    split1(x[i], h, l);
    g_xhi[i] = h;
    g_xlo[i] = l;
}

// ---------------------------------------------------------------------------
// Pipelined GEMM (layer 1 only): C[M,128] = A[M,K] @ Bt[128,K]^T (+ bias).
// OUTF16=0: fp32 out (+bias). OUTF16=1: f16 out scaled 2^-10 (no bias).
// ---------------------------------------------------------------------------
#define TILE_E (128 * LDK)
#define SMEMSZ_G (2 * 4 * TILE_E * 2)

template<int OUTF16>
__global__ void __launch_bounds__(256) tgemm_kernel(
    const __nv_bfloat16* __restrict__ Ahi, const __nv_bfloat16* __restrict__ Alo,
    const __nv_bfloat16* __restrict__ Bhi, const __nv_bfloat16* __restrict__ Blo,
    const float* __restrict__ bias, void* __restrict__ Cout, int M, int K)
{
    extern __shared__ __nv_bfloat16 sb[];
    const int tid = threadIdx.x, lane = tid & 31, wid = tid >> 5;
    const int row0 = blockIdx.x * 128;
    const int wm = wid & 3, wn = wid >> 2;

    float acc[2][8][4];
#pragma unroll
    for (int a = 0; a < 2; a++)
#pragma unroll
        for (int b = 0; b < 8; b++)
#pragma unroll
            for (int c = 0; c < 4; c++) acc[a][b][c] = 0.f;

    const int a_r = (lane & 7) + ((lane >> 3) & 1) * 8;
    const int a_c = (lane >> 4) * 8;
    const int b_r = (lane & 7) + (lane >> 4) * 8;
    const int b_c = ((lane >> 3) & 1) * 8;
    const int nc = K >> 5;

    auto load_stage = [&](int st, int k0) {
        __nv_bfloat16* sAh = sb + (st * 4 + 0) * TILE_E;
        __nv_bfloat16* sAl = sb + (st * 4 + 1) * TILE_E;
        __nv_bfloat16* sBh = sb + (st * 4 + 2) * TILE_E;
        __nv_bfloat16* sBl = sb + (st * 4 + 3) * TILE_E;
#pragma unroll
        for (int i = tid; i < 512; i += 256) {
            int r = i >> 2, g = i & 3;
            uint32_t sz = (row0 + r < M) ? 16u : 0u;
            size_t go = (size_t)(row0 + r) * K + k0 + g * 8;
            cp16(s2u(sAh + r * LDK + g * 8), Ahi + go, sz);
            cp16(s2u(sAl + r * LDK + g * 8), Alo + go, sz);
        }
#pragma unroll
        for (int i = tid; i < 512; i += 256) {
            int r = i >> 2, g = i & 3;
            size_t go = (size_t)r * K + k0 + g * 8;
            cp16(s2u(sBh + r * LDK + g * 8), Bhi + go, 16u);
            cp16(s2u(sBl + r * LDK + g * 8), Blo + go, 16u);
        }
        CP_COMMIT();
    };

    load_stage(0, 0);
    for (int c = 0; c < nc; c++) {
        if (c + 1 < nc) {
            load_stage((c + 1) & 1, (c + 1) << 5);
            asm volatile("cp.async.wait_group 1;");
        } else {
            asm volatile("cp.async.wait_group 0;");
        }
        __syncthreads();

        const int st = c & 1;
        const __nv_bfloat16* sAh = sb + (st * 4 + 0) * TILE_E;
        const __nv_bfloat16* sAl = sb + (st * 4 + 1) * TILE_E;
        const __nv_bfloat16* sBh = sb + (st * 4 + 2) * TILE_E;
        const __nv_bfloat16* sBl = sb + (st * 4 + 3) * TILE_E;
#pragma unroll
        for (int k16 = 0; k16 < 32; k16 += 16) {
            uint32_t ah[2][4], al[2][4];
#pragma unroll
            for (int mt = 0; mt < 2; mt++) {
                int er = wm * 32 + mt * 16 + a_r;
                int ec = k16 + a_c;
                ldsm4(ah[mt], s2u(sAh + er * LDK + ec));
                ldsm4(al[mt], s2u(sAl + er * LDK + ec));
            }
#pragma unroll
            for (int p = 0; p < 4; p++) {
                int er = wn * 64 + p * 16 + b_r;
                int ec = k16 + b_c;
                uint32_t bh[4], bl[4];
                ldsm4(bh, s2u(sBh + er * LDK + ec));
                ldsm4(bl, s2u(sBl + er * LDK + ec));
#pragma unroll
                for (int mt = 0; mt < 2; mt++) {
                    mma_bf16(acc[mt][2 * p],     ah[mt], bh[0], bh[1]);
                    mma_bf16(acc[mt][2 * p],     ah[mt], bl[0], bl[1]);
                    mma_bf16(acc[mt][2 * p],     al[mt], bh[0], bh[1]);
                    mma_bf16(acc[mt][2 * p + 1], ah[mt], bh[2], bh[3]);
                    mma_bf16(acc[mt][2 * p + 1], ah[mt], bl[2], bl[3]);
                    mma_bf16(acc[mt][2 * p + 1], al[mt], bh[2], bh[3]);
                }
            }
        }
        __syncthreads();
    }

    const int er0 = row0 + wm * 32 + (lane >> 2);
    const int ec0 = wn * 64 + (lane & 3) * 2;
#pragma unroll
    for (int mt = 0; mt < 2; mt++) {
#pragma unroll
        for (int nt = 0; nt < 8; nt++) {
            int col = ec0 + nt * 8;
            float bx = 0.f, by = 0.f;
            if (!OUTF16 && bias) { bx = bias[col]; by = bias[col + 1]; }
            int r1 = er0 + mt * 16, r2 = r1 + 8;
#pragma unroll
            for (int half = 0; half < 2; half++) {
                int r = half ? r2 : r1;
                if (r >= M) continue;
                float vx = acc[mt][nt][half * 2] + bx;
                float vy = acc[mt][nt][half * 2 + 1] + by;
                if (OUTF16) {
                    __half2* C = (__half2*)Cout;
                    C[((size_t)r * 128 + col) >> 1] =
                        __floats2half2_rn(vx * SUP_SCALE, vy * SUP_SCALE);
                } else {
                    float* C = (float*)Cout;
                    *(float2*)(C + (size_t)r * 128 + col) = make_float2(vx, vy);
                }
            }
        }
    }
}

// ---------------------------------------------------------------------------
// FUSED mid layer: x_{l+1} = relu(agg(x_l)@W + b) + x_l
// Phase 1: gather agg(x_l) from scaled-f16 slab -> smem A (bf16 hi/lo, LDA)
// Phase 2: GEMM with double-buffered cp.async B tiles
// Phase 3: epilogue relu+bias+residual(hist hi+lo) -> hist hi/lo + f16 slab
// ---------------------------------------------------------------------------
#define FL_A_E (128 * LDA)
#define FL_B_E (128 * LDK)
#define FL_SMEM ((2 * FL_A_E + 4 * FL_B_E) * 2)   // 110592 bytes

__global__ void __launch_bounds__(256, 2) fused_layer_kernel(
    const __half* __restrict__ src16,
    const __nv_bfloat16* __restrict__ reshi, const __nv_bfloat16* __restrict__ reslo,
    const __nv_bfloat16* __restrict__ Bhi, const __nv_bfloat16* __restrict__ Blo,
    const float* __restrict__ bias,
    __nv_bfloat16* __restrict__ outhi, __nv_bfloat16* __restrict__ outlo,
    __half* __restrict__ out16, int n)
{
    extern __shared__ __nv_bfloat16 sb[];
    __nv_bfloat16* sAh = sb;
    __nv_bfloat16* sAl = sb + FL_A_E;
    const int tid = threadIdx.x, lane = tid & 31, wid = tid >> 5;
    const int row0 = blockIdx.x * 128;
    const int wm = wid & 3, wn = wid >> 2;

    auto loadB = [&](int st, int chunk) {
        __nv_bfloat16* sBh = sb + 2 * FL_A_E + st * 2 * FL_B_E;
        __nv_bfloat16* sBl = sBh + FL_B_E;
        int k0 = chunk * 32;
#pragma unroll
        for (int i = tid; i < 512; i += 256) {
            int r = i >> 2, g = i & 3;
            size_t go = (size_t)r * 128 + k0 + g * 8;
            cp16(s2u(sBh + r * LDK + g * 8), Bhi + go, 16u);
            cp16(s2u(sBl + r * LDK + g * 8), Blo + go, 16u);
        }
        CP_COMMIT();
    };
    loadB(0, 0);
    loadB(1, 1);

    // ---- Phase 1: gather. warp wid handles rows wid*16 .. wid*16+15 ----
    const uint2* sup2 = (const uint2*)src16;
    for (int rr = 0; rr < 16; rr++) {
        int r = wid * 16 + rr;
        int grow = row0 + r;
        float4 acc = make_float4(0.f, 0.f, 0.f, 0.f);
        if (grow < n) {
            const int s = g_offs[grow], e = g_offs[grow + 1];
            int i = s;
            for (; i + 3 < e; i += 4) {
                int   si[4]; float wv[4]; uint2 u[4];
#pragma unroll
                for (int q = 0; q < 4; q++) { si[q] = g_csr_src[i + q]; wv[q] = g_csr_w[i + q]; }
#pragma unroll
                for (int q = 0; q < 4; q++) u[q] = sup2[(size_t)si[q] * 32 + lane];
#pragma unroll
                for (int q = 0; q < 4; q++) {
                    float2 a0 = __half22float2(*(const __half2*)&u[q].x);
                    float2 a1 = __half22float2(*(const __half2*)&u[q].y);
                    acc.x = fmaf(wv[q], a0.x, acc.x); acc.y = fmaf(wv[q], a0.y, acc.y);
                    acc.z = fmaf(wv[q], a1.x, acc.z); acc.w = fmaf(wv[q], a1.y, acc.w);
                }
            }
            for (; i < e; i++) {
                int s0 = g_csr_src[i];
                float w0 = g_csr_w[i];
                uint2 u0 = sup2[(size_t)s0 * 32 + lane];
                float2 a0 = __half22float2(*(const __half2*)&u0.x);
                float2 a1 = __half22float2(*(const __half2*)&u0.y);
                acc.x = fmaf(w0, a0.x, acc.x); acc.y = fmaf(w0, a0.y, acc.y);
                acc.z = fmaf(w0, a1.x, acc.z); acc.w = fmaf(w0, a1.y, acc.w);
            }
            acc.x *= SLAB_UNSCALE; acc.y *= SLAB_UNSCALE;
            acc.z *= SLAB_UNSCALE; acc.w *= SLAB_UNSCALE;
        }
        __nv_bfloat16 h0, l0, h1, l1, h2, l2, h3, l3;
        split1(acc.x, h0, l0); split1(acc.y, h1, l1);
        split1(acc.z, h2, l2); split1(acc.w, h3, l3);
        uint2 wh, wl;
        wh.x = (uint32_t)__bfloat16_as_ushort(h0) | ((uint32_t)__bfloat16_as_ushort(h1) << 16);
        wh.y = (uint32_t)__bfloat16_as_ushort(h2) | ((uint32_t)__bfloat16_as_ushort(h3) << 16);
        wl.x = (uint32_t)__bfloat16_as_ushort(l0) | ((uint32_t)__bfloat16_as_ushort(l1) << 16);
        wl.y = (uint32_t)__bfloat16_as_ushort(l2) | ((uint32_t)__bfloat16_as_ushort(l3) << 16);
        *(uint2*)(sAh + r * LDA + lane * 4) = wh;
        *(uint2*)(sAl + r * LDA + lane * 4) = wl;
    }

    // ---- Phase 2: GEMM ----
    float acc[2][8][4];
#pragma unroll
    for (int a = 0; a < 2; a++)
#pragma unroll
        for (int b = 0; b < 8; b++)
#pragma unroll
            for (int c = 0; c < 4; c++) acc[a][b][c] = 0.f;

    const int a_r = (lane & 7) + ((lane >> 3) & 1) * 8;
    const int a_c = (lane >> 4) * 8;
    const int b_r = (lane & 7) + (lane >> 4) * 8;
    const int b_c = ((lane >> 3) & 1) * 8;

    for (int c = 0; c < 4; c++) {
        if (c < 3) asm volatile("cp.async.wait_group 1;");
        else       asm volatile("cp.async.wait_group 0;");
        __syncthreads();   // first iteration also publishes smem A

        const __nv_bfloat16* sBh = sb + 2 * FL_A_E + (c & 1) * 2 * FL_B_E;
        const __nv_bfloat16* sBl = sBh + FL_B_E;
#pragma unroll
        for (int k16 = 0; k16 < 32; k16 += 16) {
            uint32_t ah[2][4], al[2][4];
#pragma unroll
            for (int mt = 0; mt < 2; mt++) {
                int er = wm * 32 + mt * 16 + a_r;
                int ec = c * 32 + k16 + a_c;
                ldsm4(ah[mt], s2u(sAh + er * LDA + ec));
                ldsm4(al[mt], s2u(sAl + er * LDA + ec));
            }
#pragma unroll
            for (int p = 0; p < 4; p++) {
                int er = wn * 64 + p * 16 + b_r;
                int ec = k16 + b_c;
                uint32_t bh[4], bl[4];
                ldsm4(bh, s2u(sBh + er * LDK + ec));
                ldsm4(bl, s2u(sBl + er * LDK + ec));
#pragma unroll
                for (int mt = 0; mt < 2; mt++) {
                    mma_bf16(acc[mt][2 * p],     ah[mt], bh[0], bh[1]);
                    mma_bf16(acc[mt][2 * p],     ah[mt], bl[0], bl[1]);
                    mma_bf16(acc[mt][2 * p],     al[mt], bh[0], bh[1]);
                    mma_bf16(acc[mt][2 * p + 1], ah[mt], bh[2], bh[3]);
                    mma_bf16(acc[mt][2 * p + 1], ah[mt], bl[2], bl[3]);
                    mma_bf16(acc[mt][2 * p + 1], al[mt], bh[2], bh[3]);
                }
            }
        }
        if (c < 2) {
            __syncthreads();        // all warps done with stage c&1
            loadB(c & 1, c + 2);
        }
    }

    // ---- Phase 3: epilogue ----
    const int er0 = row0 + wm * 32 + (lane >> 2);
    const int ec0 = wn * 64 + (lane & 3) * 2;
#pragma unroll
    for (int mt = 0; mt < 2; mt++) {
#pragma unroll
        for (int nt = 0; nt < 8; nt++) {
            int col = ec0 + nt * 8;
            float bx = bias[col], by = bias[col + 1];
            int r1 = er0 + mt * 16, r2 = r1 + 8;
#pragma unroll
            for (int half = 0; half < 2; half++) {
                int r = half ? r2 : r1;
                if (r >= n) continue;
                size_t o = (size_t)r * 128 + col;
                float vx = fmaxf(acc[mt][nt][half * 2] + bx, 0.f);
                float vy = fmaxf(acc[mt][nt][half * 2 + 1] + by, 0.f);
                float2 rh = unpack2(*(const uint32_t*)(reshi + o));
                float2 rl = unpack2(*(const uint32_t*)(reslo + o));
                vx += rh.x + rl.x;
                vy += rh.y + rl.y;
                __nv_bfloat16 hx, lx, hy, ly;
                split1(vx, hx, lx);
                split1(vy, hy, ly);
                *(uint32_t*)(outhi + o) =
                    (uint32_t)__bfloat16_as_ushort(hx) | ((uint32_t)__bfloat16_as_ushort(hy) << 16);
                *(uint32_t*)(outlo + o) =
                    (uint32_t)__bfloat16_as_ushort(lx) | ((uint32_t)__bfloat16_as_ushort(ly) << 16);
                ((__half2*)out16)[o >> 1] = __floats2half2_rn(vx * SLAB_SCALE, vy * SLAB_SCALE);
            }
        }
    }
}

// ---------------------------------------------------------------------------
// Final GEMM (fp16): C[M,40] = X_cat(scaled f16)[M,1792] @ W15f[48,1792]^T * 2^15
// ---------------------------------------------------------------------------
#define BTILE_E (48 * LDK)
#define SMEMSZ_G40F (2 * (TILE_E + 2 * BTILE_E) * 2)

__global__ void __launch_bounds__(256) tgemm40f_kernel(
    const __half* __restrict__ H16,
    const __half* __restrict__ Bh, const __half* __restrict__ Bl,
    float* __restrict__ C, int M)
{
    extern __shared__ __half sh[];
    const int tid = threadIdx.x, lane = tid & 31, wid = tid >> 5;
    const int row0 = blockIdx.x * 128;
    const size_t slabE = (size_t)M * 128;
    const int STG = TILE_E + 2 * BTILE_E;

    float acc[6][4];
#pragma unroll
    for (int a = 0; a < 6; a++)
#pragma unroll
        for (int c = 0; c < 4; c++) acc[a][c] = 0.f;

    const int a_r = (lane & 7) + ((lane >> 3) & 1) * 8;
    const int a_c = (lane >> 4) * 8;
    const int b_r = (lane & 7) + (lane >> 4) * 8;
    const int b_c = ((lane >> 3) & 1) * 8;

    auto load_stage = [&](int st, int c) {
        const int k0g = c * 32;
        const int slab = 13 - (k0g >> 7);
        const int kin = k0g & 127;
        const __half* A = H16 + (size_t)slab * slabE;
        __half* sA = sh + st * STG;
        __half* sBh = sA + TILE_E;
        __half* sBl = sBh + BTILE_E;
#pragma unroll
        for (int i = tid; i < 512; i += 256) {
            int r = i >> 2, g = i & 3;
            uint32_t sz = (row0 + r < M) ? 16u : 0u;
            size_t go = (size_t)(row0 + r) * 128 + kin + g * 8;
            cp16(s2u(sA + r * LDK + g * 8), A + go, sz);
        }
        if (tid < 192) {
            int r = tid >> 2, g = tid & 3;
            size_t go = (size_t)r * 1792 + k0g + g * 8;
            cp16(s2u(sBh + r * LDK + g * 8), Bh + go, 16u);
            cp16(s2u(sBl + r * LDK + g * 8), Bl + go, 16u);
        }
        CP_COMMIT();
    };

    load_stage(0, 0);
    for (int c = 0; c < 56; c++) {
        if (c + 1 < 56) {
            load_stage((c + 1) & 1, c + 1);
            asm volatile("cp.async.wait_group 1;");
        } else {
            asm volatile("cp.async.wait_group 0;");
        }
        __syncthreads();

        const int st = c & 1;
        const __half* sA = sh + st * STG;
        const __half* sBh = sA + TILE_E;
        const __half* sBl = sBh + BTILE_E;
#pragma unroll
        for (int k16 = 0; k16 < 32; k16 += 16) {
            uint32_t a[4];
            int er = wid * 16 + a_r;
            int ec = k16 + a_c;
            ldsm4(a, s2u(sA + er * LDK + ec));
#pragma unroll
            for (int p = 0; p < 3; p++) {
                int br = p * 16 + b_r;
                int bc = k16 + b_c;
                uint32_t bh[4], bl[4];
                ldsm4(bh, s2u(sBh + br * LDK + bc));
                ldsm4(bl, s2u(sBl + br * LDK + bc));
                mma_fp16(acc[2 * p],     a, bh[0], bh[1]);
                mma_fp16(acc[2 * p],     a, bl[0], bl[1]);
                mma_fp16(acc[2 * p + 1], a, bh[2], bh[3]);
                mma_fp16(acc[2 * p + 1], a, bl[2], bl[3]);
            }
        }
        __syncthreads();
    }
    const int r1 = row0 + wid * 16 + (lane >> 2);
    const int r2 = r1 + 8;
#pragma unroll
    for (int nt = 0; nt < 5; nt++) {
        int col = nt * 8 + (lane & 3) * 2;
        if (r1 < M) *(float2*)(C + (size_t)r1 * 40 + col) =
            make_float2(acc[nt][0] * SLAB_UNSCALE, acc[nt][1] * SLAB_UNSCALE);
        if (r2 < M) *(float2*)(C + (size_t)r2 * 40 + col) =
            make_float2(acc[nt][2] * SLAB_UNSCALE, acc[nt][3] * SLAB_UNSCALE);
    }
}

// ---------------------------------------------------------------------------
// Layer-1 aggregation: x1 = relu(agg(sup)*2^10 + b1) + z.
// Writes hist slab0 hi/lo + f16 slab0 (2^-15).
// ---------------------------------------------------------------------------
__global__ void __launch_bounds__(256) agg1_kernel(
    const __half* __restrict__ support, const float* __restrict__ bias,
    const float* __restrict__ z,
    __nv_bfloat16* __restrict__ outhi, __nv_bfloat16* __restrict__ outlo,
    __half* __restrict__ out16, int n)
{
    const int node = (blockIdx.x * blockDim.x + threadIdx.x) >> 5;
    if (node >= n) return;
    const int lane = threadIdx.x & 31;
    const int s = g_offs[node], e = g_offs[node + 1];
    const uint2* sup2 = (const uint2*)support;

    float4 acc = make_float4(0.f, 0.f, 0.f, 0.f);
    int i = s;
    for (; i + 1 < e; i += 2) {
        int s0 = g_csr_src[i], s1 = g_csr_src[i + 1];
        float w0 = g_csr_w[i],  w1 = g_csr_w[i + 1];
        uint2 u0 = sup2[(size_t)s0 * 32 + lane];
        uint2 u1 = sup2[(size_t)s1 * 32 + lane];
        float2 a0 = __half22float2(*(const __half2*)&u0.x);
        float2 a1 = __half22float2(*(const __half2*)&u0.y);
        acc.x = fmaf(w0, a0.x, acc.x); acc.y = fmaf(w0, a0.y, acc.y);
        acc.z = fmaf(w0, a1.x, acc.z); acc.w = fmaf(w0, a1.y, acc.w);
        float2 b0 = __half22float2(*(const __half2*)&u1.x);
        float2 b1 = __half22float2(*(const __half2*)&u1.y);
        acc.x = fmaf(w1, b0.x, acc.x); acc.y = fmaf(w1, b0.y, acc.y);
        acc.z = fmaf(w1, b1.x, acc.z); acc.w = fmaf(w1, b1.y, acc.w);
    }
    if (i < e) {
        int s0 = g_csr_src[i];
        float w0 = g_csr_w[i];
        uint2 u0 = sup2[(size_t)s0 * 32 + lane];
        float2 a0 = __half22float2(*(const __half2*)&u0.x);
        float2 a1 = __half22float2(*(const __half2*)&u0.y);
        acc.x = fmaf(w0, a0.x, acc.x); acc.y = fmaf(w0, a0.y, acc.y);
        acc.z = fmaf(w0, a1.x, acc.z); acc.w = fmaf(w0, a1.y, acc.w);
    }
    acc.x *= SUP_UNSCALE; acc.y *= SUP_UNSCALE;
    acc.z *= SUP_UNSCALE; acc.w *= SUP_UNSCALE;

    float4 b = ((const float4*)bias)[lane];
    float4 r = ((const float4*)z)[(size_t)node * 32 + lane];
    float4 o;
    o.x = fmaxf(acc.x + b.x, 0.f) + r.x;
    o.y = fmaxf(acc.y + b.y, 0.f) + r.y;
    o.z = fmaxf(acc.z + b.z, 0.f) + r.z;
    o.w = fmaxf(acc.w + b.w, 0.f) + r.w;

    __nv_bfloat16 h0, l0, h1, l1, h2, l2, h3, l3;
    split1(o.x, h0, l0); split1(o.y, h1, l1);
    split1(o.z, h2, l2); split1(o.w, h3, l3);
    uint2 wh, wl;
    wh.x = (uint32_t)__bfloat16_as_ushort(h0) | ((uint32_t)__bfloat16_as_ushort(h1) << 16);
    wh.y = (uint32_t)__bfloat16_as_ushort(h2) | ((uint32_t)__bfloat16_as_ushort(h3) << 16);
    wl.x = (uint32_t)__bfloat16_as_ushort(l0) | ((uint32_t)__bfloat16_as_ushort(l1) << 16);
    wl.y = (uint32_t)__bfloat16_as_ushort(l2) | ((uint32_t)__bfloat16_as_ushort(l3) << 16);
    ((uint2*)(outhi + (size_t)node * 128))[lane] = wh;
    ((uint2*)(outlo + (size_t)node * 128))[lane] = wl;
    __half2 f0 = __floats2half2_rn(o.x * SLAB_SCALE, o.y * SLAB_SCALE);
    __half2 f1 = __floats2half2_rn(o.z * SLAB_SCALE, o.w * SLAB_SCALE);
    __half2* o16 = (__half2*)(out16 + (size_t)node * 128);
    o16[lane * 2]     = f0;
    o16[lane * 2 + 1] = f1;
}

// ---------------------------------------------------------------------------
// Final: agg40 + b15 + log_softmax. Warp per node. fp32 gather.
// ---------------------------------------------------------------------------
__global__ void __launch_bounds__(256) spmm40_lsm_kernel(
    const float* __restrict__ accum, const float* __restrict__ b15,
    float* __restrict__ out, int n)
{
    const int node = (blockIdx.x * blockDim.x + threadIdx.x) >> 5;
    if (node >= n) return;
    const int lane = threadIdx.x & 31;
    const int s = g_offs[node], e = g_offs[node + 1];

    float a1 = 0.f, a2 = 0.f;
    for (int i = s; i < e; i++) {
        int src = g_csr_src[i];
        float w = g_csr_w[i];
        const float* row = accum + (size_t)src * 40;
        a1 = fmaf(w, row[lane], a1);
        if (lane < 8) a2 = fmaf(w, row[32 + lane], a2);
    }
    float v1 = a1 + b15[lane];
    float v2 = (lane < 8) ? (a2 + b15[32 + lane]) : -3.0e38f;

    float m = fmaxf(v1, v2);
#pragma unroll
    for (int o = 16; o > 0; o >>= 1) m = fmaxf(m, __shfl_xor_sync(0xffffffffu, m, o));
    float sum = expf(v1 - m) + ((lane < 8) ? expf(v2 - m) : 0.f);
#pragma unroll
    for (int o = 16; o > 0; o >>= 1) sum += __shfl_xor_sync(0xffffffffu, sum, o);
    float ls = m + logf(sum);

    out[(size_t)node * 40 + lane] = v1 - ls;
    if (lane < 8) out[(size_t)node * 40 + 32 + lane] = v2 - ls;
}

// ---------------------------------------------------------------------------
// Launch
// ---------------------------------------------------------------------------
extern "C" void kernel_launch(void* const* d_in, const int* in_sizes, int n_in,
                              void* d_out, int out_size)
{
    const float* x    = (const float*)d_in[0];
    const int*   esrc = (const int*)  d_in[1];
    const int*   edst = (const int*)  d_in[2];
    const float* ew   = (const float*)d_in[3];
    const float* W0   = (const float*)d_in[4];
    const float* b0   = (const float*)d_in[5];
    const float* W1   = (const float*)d_in[6];
    const float* b1   = (const float*)d_in[7];
    const float* Wmid = (const float*)d_in[8];
    const float* bmid = (const float*)d_in[9];
    const float* W15  = (const float*)d_in[10];
    const float* b15  = (const float*)d_in[11];

    const int E = in_sizes[1];
    const int n = in_sizes[0] / 256;
    float* out = (float*)d_out;

    float *z, *accum;
    __half *sup, *hf16, *w15fh, *w15fl;
    __nv_bfloat16 *wthi, *wtlo, *xhi, *xlo, *hhi, *hlo;
    cudaGetSymbolAddress((void**)&z,     g_z);
    cudaGetSymbolAddress((void**)&sup,   g_sup);
    cudaGetSymbolAddress((void**)&accum, g_acc);
    cudaGetSymbolAddress((void**)&wthi,  g_wthi);
    cudaGetSymbolAddress((void**)&wtlo,  g_wtlo);
    cudaGetSymbolAddress((void**)&w15fh, g_w15fh);
    cudaGetSymbolAddress((void**)&w15fl, g_w15fl);
    cudaGetSymbolAddress((void**)&xhi,   g_xhi);
    cudaGetSymbolAddress((void**)&xlo,   g_xlo);
    cudaGetSymbolAddress((void**)&hhi,   g_hhi);
    cudaGetSymbolAddress((void**)&hlo,   g_hlo);
    cudaGetSymbolAddress((void**)&hf16,  g_hf16);

    cudaFuncSetAttribute(tgemm_kernel<0>,   cudaFuncAttributeMaxDynamicSharedMemorySize, SMEMSZ_G);
    cudaFuncSetAttribute(tgemm_kernel<1>,   cudaFuncAttributeMaxDynamicSharedMemorySize, SMEMSZ_G);
    cudaFuncSetAttribute(fused_layer_kernel, cudaFuncAttributeMaxDynamicSharedMemorySize, FL_SMEM);
    cudaFuncSetAttribute(tgemm40f_kernel,   cudaFuncAttributeMaxDynamicSharedMemorySize, SMEMSZ_G40F);

    const int TB = 256;
    const int gridE = (E + TB - 1) / TB;
    const int gridN = (n + TB - 1) / TB;
    const int gridT = (n + 127) / 128;
    const int gridSpmm = (n + 7) / 8;
    const size_t slab = (size_t)n * 128;

    // 1. CSR build + splits
    zero_deg_kernel<<<gridN, TB>>>(n);
    hist_kernel<<<gridE, TB>>>(edst, E);
    scan_kernel<<<1, 1024>>>(n);
    scatter_kernel<<<gridE, TB>>>(esrc, edst, ew, E);
    split_w_kernel<<<(WT_TOTAL + TB - 1) / TB, TB>>>(W0, W1, Wmid, W15);
    split_x_kernel<<<(n * 256 + TB - 1) / TB, TB>>>(x, n * 256);

    // 2. layer 1
    tgemm_kernel<0><<<gridT, 256, SMEMSZ_G>>>(xhi, xlo, wthi + WOFF_W0, wtlo + WOFF_W0, b0, z, n, 256);
    tgemm_kernel<1><<<gridT, 256, SMEMSZ_G>>>(xhi, xlo, wthi + WOFF_W1, wtlo + WOFF_W1, nullptr, sup, n, 256);
    agg1_kernel<<<gridSpmm, 256>>>(sup, b1, z, hhi, hlo, hf16, n);

    // 3. mid layers: one fused kernel each
    for (int l = 0; l < 13; l++) {
        fused_layer_kernel<<<gridT, 256, FL_SMEM>>>(
            hf16 + (size_t)l * slab,
            hhi + (size_t)l * slab, hlo + (size_t)l * slab,
            wthi + WOFF_MID + (size_t)l * 16384, wtlo + WOFF_MID + (size_t)l * 16384,
            bmid + (size_t)l * 128,
            hhi + (size_t)(l + 1) * slab, hlo + (size_t)(l + 1) * slab,
            hf16 + (size_t)(l + 1) * slab, n);
    }

    // 4. P = X_cat @ W15 (fp16 path)
    tgemm40f_kernel<<<gridT, 256, SMEMSZ_G40F>>>(hf16, w15fh, w15fl, accum, n);

    // 5. out = log_softmax(agg40(P) + b15)
    spmm40_lsm_kernel<<<gridSpmm, 256>>>(accum, b15, out, n);
}

// round 10
// speedup vs baseline: 2.1812x; 2.1812x over previous
#include <cuda_runtime.h>
#include <cuda_bf16.h>
#include <cuda_fp16.h>
#include <math.h>
#include <stdint.h>

// ---------------------------------------------------------------------------
// ResGCN15 (sm_103 -> HMMA mma.sync).
// R7 pipeline shape (separate GEMM / agg kernels — R9 fusion regressed) with:
//  - activations stored ONLY as scaled f16 slabs (2^-15), feeding both the
//    next mid GEMM (A operand, fp16 MMA w/ f16 hi/lo weights) and final GEMM
//  - residual path in fp32 h (exact)
//  - layer-1 GEMMs keep bf16 hi/lo split (x is full-precision input)
//  - fp16 final GEMM over the 14 slabs
// ---------------------------------------------------------------------------

#define MAX_N 50000
#define MAX_E 800000
#define NHID 128
#define NCLASS 40
#define LDK 40          // smem row stride (32 elems + 8 pad)

#define SUP_SCALE    0.0009765625f      // 2^-10 (sup stream)
#define SUP_UNSCALE  1024.0f
#define SLAB_SCALE   0.000030517578125f // 2^-15 (activation slabs)
#define SLAB_UNSCALE 32768.0f
#define ACC2SUP      32.0f              // 2^15 * 2^-10

#define WOFF_W0   0
#define WOFF_W1   32768
#define WOFF_MID  65536
#define WOFF_W15  278528
#define WT_TOTAL  364544

__device__ __align__(16) int   g_deg[MAX_N];
__device__ __align__(16) int   g_offs[MAX_N + 1];
__device__ __align__(16) int   g_cursor[MAX_N];
__device__ __align__(16) int   g_csr_src[MAX_E];
__device__ __align__(16) float g_csr_w[MAX_E];
__device__ __align__(16) float g_z[(size_t)MAX_N * NHID];
__device__ __align__(16) float g_h[(size_t)MAX_N * NHID];
__device__ __align__(16) __half g_sup[(size_t)MAX_N * NHID];
__device__ __align__(16) float g_acc[(size_t)MAX_N * NCLASS];
__device__ __align__(16) __nv_bfloat16 g_wthi[WT_TOTAL];
__device__ __align__(16) __nv_bfloat16 g_wtlo[WT_TOTAL];
__device__ __align__(16) __half g_wfh[WT_TOTAL];
__device__ __align__(16) __half g_wfl[WT_TOTAL];
__device__ __align__(16) __nv_bfloat16 g_xhi[(size_t)MAX_N * 256];
__device__ __align__(16) __nv_bfloat16 g_xlo[(size_t)MAX_N * 256];
__device__ __align__(16) __half g_hf16[(size_t)14 * MAX_N * NHID];  // 2^-15

// ---------------------------------------------------------------------------
// helpers
// ---------------------------------------------------------------------------
__device__ __forceinline__ uint32_t s2u(const void* p) {
    return (uint32_t)__cvta_generic_to_shared(p);
}
__device__ __forceinline__ void ldsm4(uint32_t* r, uint32_t addr) {
    asm volatile("ldmatrix.sync.aligned.m8n8.x4.shared.b16 {%0,%1,%2,%3}, [%4];"
                 : "=r"(r[0]), "=r"(r[1]), "=r"(r[2]), "=r"(r[3]) : "r"(addr));
}
__device__ __forceinline__ void mma_bf16(float* d, const uint32_t* a,
                                         uint32_t b0, uint32_t b1) {
    asm volatile(
        "mma.sync.aligned.m16n8k16.row.col.f32.bf16.bf16.f32 "
        "{%0,%1,%2,%3}, {%4,%5,%6,%7}, {%8,%9}, {%0,%1,%2,%3};"
        : "+f"(d[0]), "+f"(d[1]), "+f"(d[2]), "+f"(d[3])
        : "r"(a[0]), "r"(a[1]), "r"(a[2]), "r"(a[3]), "r"(b0), "r"(b1));
}
__device__ __forceinline__ void mma_fp16(float* d, const uint32_t* a,
                                         uint32_t b0, uint32_t b1) {
    asm volatile(
        "mma.sync.aligned.m16n8k16.row.col.f32.f16.f16.f32 "
        "{%0,%1,%2,%3}, {%4,%5,%6,%7}, {%8,%9}, {%0,%1,%2,%3};"
        : "+f"(d[0]), "+f"(d[1]), "+f"(d[2]), "+f"(d[3])
        : "r"(a[0]), "r"(a[1]), "r"(a[2]), "r"(a[3]), "r"(b0), "r"(b1));
}
__device__ __forceinline__ void split1(float v, __nv_bfloat16& h, __nv_bfloat16& l) {
    h = __float2bfloat16(v);
    l = __float2bfloat16(v - __bfloat162float(h));
}
__device__ __forceinline__ void cp16(uint32_t saddr, const void* gptr, uint32_t sz) {
    asm volatile("cp.async.cg.shared.global [%0], [%1], 16, %2;"
                 :: "r"(saddr), "l"(gptr), "r"(sz));
}
#define CP_COMMIT() asm volatile("cp.async.commit_group;")

// ---------------------------------------------------------------------------
// CSR build
// ---------------------------------------------------------------------------
__global__ void zero_deg_kernel(int n) {
    int i = blockIdx.x * blockDim.x + threadIdx.x;
    if (i < n) g_deg[i] = 0;
}
__global__ void hist_kernel(const int* __restrict__ dst, int E) {
    int i = blockIdx.x * blockDim.x + threadIdx.x;
    if (i < E) atomicAdd(&g_deg[dst[i]], 1);
}
__global__ void scan_kernel(int n) {
    __shared__ int sums[1024];
    const int t = threadIdx.x;
    const int chunk = (n + 1023) >> 10;
    const int begin = t * chunk;
    const int end = min(begin + chunk, n);
    int s = 0;
    for (int i = begin; i < end; i++) s += g_deg[i];
    sums[t] = s;
    __syncthreads();
    for (int d = 1; d < 1024; d <<= 1) {
        int v = (t >= d) ? sums[t - d] : 0;
        __syncthreads();
        sums[t] += v;
        __syncthreads();
    }
    int run = (t == 0) ? 0 : sums[t - 1];
    if (t == 0) g_offs[0] = 0;
    for (int i = begin; i < end; i++) {
        g_cursor[i] = run;
        run += g_deg[i];
        g_offs[i + 1] = run;
    }
}
__global__ void scatter_kernel(const int* __restrict__ src, const int* __restrict__ dst,
                               const float* __restrict__ w, int E) {
    int i = blockIdx.x * blockDim.x + threadIdx.x;
    if (i < E) {
        int d = dst[i];
        int pos = atomicAdd(&g_cursor[d], 1);
        g_csr_src[pos] = src[i];
        g_csr_w[pos] = w[i];
    }
}

// ---------------------------------------------------------------------------
// prep: weights transposed; bf16 hi/lo (layer-1) + f16 hi/lo (mid + W15)
// ---------------------------------------------------------------------------
__global__ void split_w_kernel(const float* __restrict__ W0, const float* __restrict__ W1,
                               const float* __restrict__ Wmid, const float* __restrict__ W15) {
    int i = blockIdx.x * blockDim.x + threadIdx.x;
    if (i >= WT_TOTAL) return;
    float v;
    if (i < 32768) {
        int n = i >> 8, k = i & 255;
        v = W0[k * 128 + n];
    } else if (i < 65536) {
        int j = i - 32768;
        int n = j >> 8, k = j & 255;
        v = W1[k * 128 + n];
    } else if (i < 278528) {
        int j = i - 65536;
        int l = j >> 14, jj = j & 16383;
        int n = jj >> 7, k = jj & 127;
        v = Wmid[l * 16384 + k * 128 + n];
    } else {
        int j = i - 278528;
        int n = j / 1792, k = j % 1792;
        v = (n < 40) ? W15[(size_t)k * 40 + n] : 0.f;
    }
    __nv_bfloat16 h, l;
    split1(v, h, l);
    g_wthi[i] = h;
    g_wtlo[i] = l;
    __half fh = __float2half_rn(v);
    __half fl = __float2half_rn(v - __half2float(fh));
    g_wfh[i] = fh;
    g_wfl[i] = fl;
}
__global__ void split_x_kernel(const float* __restrict__ x, int total) {
    int i = blockIdx.x * blockDim.x + threadIdx.x;
    if (i >= total) return;
    __nv_bfloat16 h, l;
    split1(x[i], h, l);
    g_xhi[i] = h;
    g_xlo[i] = l;
}

// ---------------------------------------------------------------------------
// Pipelined bf16-split GEMM (layer 1): C[M,128] = A[M,K] @ Bt[128,K]^T.
// OUTF16=0: fp32 out (+bias). OUTF16=1: f16 out scaled 2^-10 (no bias).
// ---------------------------------------------------------------------------
#define TILE_E (128 * LDK)
#define SMEMSZ_G (2 * 4 * TILE_E * 2)

template<int OUTF16>
__global__ void __launch_bounds__(256) tgemm_kernel(
    const __nv_bfloat16* __restrict__ Ahi, const __nv_bfloat16* __restrict__ Alo,
    const __nv_bfloat16* __restrict__ Bhi, const __nv_bfloat16* __restrict__ Blo,
    const float* __restrict__ bias, void* __restrict__ Cout, int M, int K)
{
    extern __shared__ __nv_bfloat16 sb[];
    const int tid = threadIdx.x, lane = tid & 31, wid = tid >> 5;
    const int row0 = blockIdx.x * 128;
    const int wm = wid & 3, wn = wid >> 2;

    float acc[2][8][4];
#pragma unroll
    for (int a = 0; a < 2; a++)
#pragma unroll
        for (int b = 0; b < 8; b++)
#pragma unroll
            for (int c = 0; c < 4; c++) acc[a][b][c] = 0.f;

    const int a_r = (lane & 7) + ((lane >> 3) & 1) * 8;
    const int a_c = (lane >> 4) * 8;
    const int b_r = (lane & 7) + (lane >> 4) * 8;
    const int b_c = ((lane >> 3) & 1) * 8;
    const int nc = K >> 5;

    auto load_stage = [&](int st, int k0) {
        __nv_bfloat16* sAh = sb + (st * 4 + 0) * TILE_E;
        __nv_bfloat16* sAl = sb + (st * 4 + 1) * TILE_E;
        __nv_bfloat16* sBh = sb + (st * 4 + 2) * TILE_E;
        __nv_bfloat16* sBl = sb + (st * 4 + 3) * TILE_E;
#pragma unroll
        for (int i = tid; i < 512; i += 256) {
            int r = i >> 2, g = i & 3;
            uint32_t sz = (row0 + r < M) ? 16u : 0u;
            size_t go = (size_t)(row0 + r) * K + k0 + g * 8;
            cp16(s2u(sAh + r * LDK + g * 8), Ahi + go, sz);
            cp16(s2u(sAl + r * LDK + g * 8), Alo + go, sz);
        }
#pragma unroll
        for (int i = tid; i < 512; i += 256) {
            int r = i >> 2, g = i & 3;
            size_t go = (size_t)r * K + k0 + g * 8;
            cp16(s2u(sBh + r * LDK + g * 8), Bhi + go, 16u);
            cp16(s2u(sBl + r * LDK + g * 8), Blo + go, 16u);
        }
        CP_COMMIT();
    };

    load_stage(0, 0);
    for (int c = 0; c < nc; c++) {
        if (c + 1 < nc) {
            load_stage((c + 1) & 1, (c + 1) << 5);
            asm volatile("cp.async.wait_group 1;");
        } else {
            asm volatile("cp.async.wait_group 0;");
        }
        __syncthreads();

        const int st = c & 1;
        const __nv_bfloat16* sAh = sb + (st * 4 + 0) * TILE_E;
        const __nv_bfloat16* sAl = sb + (st * 4 + 1) * TILE_E;
        const __nv_bfloat16* sBh = sb + (st * 4 + 2) * TILE_E;
        const __nv_bfloat16* sBl = sb + (st * 4 + 3) * TILE_E;
#pragma unroll
        for (int k16 = 0; k16 < 32; k16 += 16) {
            uint32_t ah[2][4], al[2][4];
#pragma unroll
            for (int mt = 0; mt < 2; mt++) {
                int er = wm * 32 + mt * 16 + a_r;
                int ec = k16 + a_c;
                ldsm4(ah[mt], s2u(sAh + er * LDK + ec));
                ldsm4(al[mt], s2u(sAl + er * LDK + ec));
            }
#pragma unroll
            for (int p = 0; p < 4; p++) {
                int er = wn * 64 + p * 16 + b_r;
                int ec = k16 + b_c;
                uint32_t bh[4], bl[4];
                ldsm4(bh, s2u(sBh + er * LDK + ec));
                ldsm4(bl, s2u(sBl + er * LDK + ec));
#pragma unroll
                for (int mt = 0; mt < 2; mt++) {
                    mma_bf16(acc[mt][2 * p],     ah[mt], bh[0], bh[1]);
                    mma_bf16(acc[mt][2 * p],     ah[mt], bl[0], bl[1]);
                    mma_bf16(acc[mt][2 * p],     al[mt], bh[0], bh[1]);
                    mma_bf16(acc[mt][2 * p + 1], ah[mt], bh[2], bh[3]);
                    mma_bf16(acc[mt][2 * p + 1], ah[mt], bl[2], bl[3]);
                    mma_bf16(acc[mt][2 * p + 1], al[mt], bh[2], bh[3]);
                }
            }
        }
        __syncthreads();
    }

    const int er0 = row0 + wm * 32 + (lane >> 2);
    const int ec0 = wn * 64 + (lane & 3) * 2;
#pragma unroll
    for (int mt = 0; mt < 2; mt++) {
#pragma unroll
        for (int nt = 0; nt < 8; nt++) {
            int col = ec0 + nt * 8;
            float bx = 0.f, by = 0.f;
            if (!OUTF16 && bias) { bx = bias[col]; by = bias[col + 1]; }
            int r1 = er0 + mt * 16, r2 = r1 + 8;
#pragma unroll
            for (int half = 0; half < 2; half++) {
                int r = half ? r2 : r1;
                if (r >= M) continue;
                float vx = acc[mt][nt][half * 2] + bx;
                float vy = acc[mt][nt][half * 2 + 1] + by;
                if (OUTF16) {
                    __half2* C = (__half2*)Cout;
                    C[((size_t)r * 128 + col) >> 1] =
                        __floats2half2_rn(vx * SUP_SCALE, vy * SUP_SCALE);
                } else {
                    float* C = (float*)Cout;
                    *(float2*)(C + (size_t)r * 128 + col) = make_float2(vx, vy);
                }
            }
        }
    }
}

// ---------------------------------------------------------------------------
// Mid-layer fp16 GEMM: sup = x_l @ W.  A = f16 slab (2^-15), B = W f16 hi/lo.
// Output sup f16 scaled 2^-10 (acc * 2^5).  2 fp16 MMAs per term.
// ---------------------------------------------------------------------------
#define SMEMSZ_GF (2 * 3 * TILE_E * 2)

__global__ void __launch_bounds__(256) tgemmf_kernel(
    const __half* __restrict__ A16,
    const __half* __restrict__ Bh16, const __half* __restrict__ Bl16,
    __half* __restrict__ Cout, int M)
{
    extern __shared__ __half sh[];
    const int tid = threadIdx.x, lane = tid & 31, wid = tid >> 5;
    const int row0 = blockIdx.x * 128;
    const int wm = wid & 3, wn = wid >> 2;

    float acc[2][8][4];
#pragma unroll
    for (int a = 0; a < 2; a++)
#pragma unroll
        for (int b = 0; b < 8; b++)
#pragma unroll
            for (int c = 0; c < 4; c++) acc[a][b][c] = 0.f;

    const int a_r = (lane & 7) + ((lane >> 3) & 1) * 8;
    const int a_c = (lane >> 4) * 8;
    const int b_r = (lane & 7) + (lane >> 4) * 8;
    const int b_c = ((lane >> 3) & 1) * 8;

    auto load_stage = [&](int st, int k0) {
        __half* sA  = sh + st * 3 * TILE_E;
        __half* sBh = sA + TILE_E;
        __half* sBl = sBh + TILE_E;
#pragma unroll
        for (int i = tid; i < 512; i += 256) {
            int r = i >> 2, g = i & 3;
            uint32_t sz = (row0 + r < M) ? 16u : 0u;
            size_t go = (size_t)(row0 + r) * 128 + k0 + g * 8;
            cp16(s2u(sA + r * LDK + g * 8), A16 + go, sz);
        }
#pragma unroll
        for (int i = tid; i < 512; i += 256) {
            int r = i >> 2, g = i & 3;
            size_t go = (size_t)r * 128 + k0 + g * 8;
            cp16(s2u(sBh + r * LDK + g * 8), Bh16 + go, 16u);
            cp16(s2u(sBl + r * LDK + g * 8), Bl16 + go, 16u);
        }
        CP_COMMIT();
    };

    load_stage(0, 0);
    for (int c = 0; c < 4; c++) {
        if (c + 1 < 4) {
            load_stage((c + 1) & 1, (c + 1) << 5);
            asm volatile("cp.async.wait_group 1;");
        } else {
            asm volatile("cp.async.wait_group 0;");
        }
        __syncthreads();

        const int st = c & 1;
        const __half* sA  = sh + st * 3 * TILE_E;
        const __half* sBh = sA + TILE_E;
        const __half* sBl = sBh + TILE_E;
#pragma unroll
        for (int k16 = 0; k16 < 32; k16 += 16) {
            uint32_t a[2][4];
#pragma unroll
            for (int mt = 0; mt < 2; mt++) {
                int er = wm * 32 + mt * 16 + a_r;
                int ec = k16 + a_c;
                ldsm4(a[mt], s2u(sA + er * LDK + ec));
            }
#pragma unroll
            for (int p = 0; p < 4; p++) {
                int er = wn * 64 + p * 16 + b_r;
                int ec = k16 + b_c;
                uint32_t bh[4], bl[4];
                ldsm4(bh, s2u(sBh + er * LDK + ec));
                ldsm4(bl, s2u(sBl + er * LDK + ec));
#pragma unroll
                for (int mt = 0; mt < 2; mt++) {
                    mma_fp16(acc[mt][2 * p],     a[mt], bh[0], bh[1]);
                    mma_fp16(acc[mt][2 * p],     a[mt], bl[0], bl[1]);
                    mma_fp16(acc[mt][2 * p + 1], a[mt], bh[2], bh[3]);
                    mma_fp16(acc[mt][2 * p + 1], a[mt], bl[2], bl[3]);
                }
            }
        }
        __syncthreads();
    }

    const int er0 = row0 + wm * 32 + (lane >> 2);
    const int ec0 = wn * 64 + (lane & 3) * 2;
#pragma unroll
    for (int mt = 0; mt < 2; mt++) {
#pragma unroll
        for (int nt = 0; nt < 8; nt++) {
            int col = ec0 + nt * 8;
            int r1 = er0 + mt * 16, r2 = r1 + 8;
#pragma unroll
            for (int half = 0; half < 2; half++) {
                int r = half ? r2 : r1;
                if (r >= M) continue;
                float vx = acc[mt][nt][half * 2] * ACC2SUP;
                float vy = acc[mt][nt][half * 2 + 1] * ACC2SUP;
                ((__half2*)Cout)[((size_t)r * 128 + col) >> 1] =
                    __floats2half2_rn(vx, vy);
            }
        }
    }
}

// ---------------------------------------------------------------------------
// SpMM d=128: warp per node, f16 sup gather (2^-10).
// out = relu(agg*2^10 + bias) + res (fp32) ; also writes f16 slab (2^-15).
// res may alias out.
// ---------------------------------------------------------------------------
__global__ void __launch_bounds__(256) spmm_relu_res_kernel(
    const __half* __restrict__ support, const float* __restrict__ bias,
    const float* __restrict__ res, float* __restrict__ out,
    __half* __restrict__ out16, int n)
{
    const int node = (blockIdx.x * blockDim.x + threadIdx.x) >> 5;
    if (node >= n) return;
    const int lane = threadIdx.x & 31;
    const int s = g_offs[node], e = g_offs[node + 1];
    const uint2* sup2 = (const uint2*)support;

    float4 acc = make_float4(0.f, 0.f, 0.f, 0.f);
    int i = s;
    for (; i + 1 < e; i += 2) {
        int s0 = g_csr_src[i], s1 = g_csr_src[i + 1];
        float w0 = g_csr_w[i],  w1 = g_csr_w[i + 1];
        uint2 u0 = sup2[(size_t)s0 * 32 + lane];
        uint2 u1 = sup2[(size_t)s1 * 32 + lane];
        float2 a0 = __half22float2(*(const __half2*)&u0.x);
        float2 a1 = __half22float2(*(const __half2*)&u0.y);
        acc.x = fmaf(w0, a0.x, acc.x); acc.y = fmaf(w0, a0.y, acc.y);
        acc.z = fmaf(w0, a1.x, acc.z); acc.w = fmaf(w0, a1.y, acc.w);
        float2 b0 = __half22float2(*(const __half2*)&u1.x);
        float2 b1 = __half22float2(*(const __half2*)&u1.y);
        acc.x = fmaf(w1, b0.x, acc.x); acc.y = fmaf(w1, b0.y, acc.y);
        acc.z = fmaf(w1, b1.x, acc.z); acc.w = fmaf(w1, b1.y, acc.w);
    }
    if (i < e) {
        int s0 = g_csr_src[i];
        float w0 = g_csr_w[i];
        uint2 u0 = sup2[(size_t)s0 * 32 + lane];
        float2 a0 = __half22float2(*(const __half2*)&u0.x);
        float2 a1 = __half22float2(*(const __half2*)&u0.y);
        acc.x = fmaf(w0, a0.x, acc.x); acc.y = fmaf(w0, a0.y, acc.y);
        acc.z = fmaf(w0, a1.x, acc.z); acc.w = fmaf(w0, a1.y, acc.w);
    }
    acc.x *= SUP_UNSCALE; acc.y *= SUP_UNSCALE;
    acc.z *= SUP_UNSCALE; acc.w *= SUP_UNSCALE;

    float4 b = ((const float4*)bias)[lane];
    float4 r = ((const float4*)res)[(size_t)node * 32 + lane];
    float4 o;
    o.x = fmaxf(acc.x + b.x, 0.f) + r.x;
    o.y = fmaxf(acc.y + b.y, 0.f) + r.y;
    o.z = fmaxf(acc.z + b.z, 0.f) + r.z;
    o.w = fmaxf(acc.w + b.w, 0.f) + r.w;
    ((float4*)out)[(size_t)node * 32 + lane] = o;

    uint2 w16;
    __half2 f0 = __floats2half2_rn(o.x * SLAB_SCALE, o.y * SLAB_SCALE);
    __half2 f1 = __floats2half2_rn(o.z * SLAB_SCALE, o.w * SLAB_SCALE);
    w16.x = *(uint32_t*)&f0;
    w16.y = *(uint32_t*)&f1;
    ((uint2*)(out16 + (size_t)node * 128))[lane] = w16;
}

// ---------------------------------------------------------------------------
// Final GEMM (fp16): C[M,40] = X_cat(f16, 2^-15)[M,1792] @ W15f[48,1792]^T * 2^15
// ---------------------------------------------------------------------------
#define BTILE_E (48 * LDK)
#define SMEMSZ_G40F (2 * (TILE_E + 2 * BTILE_E) * 2)

__global__ void __launch_bounds__(256) tgemm40f_kernel(
    const __half* __restrict__ H16,
    const __half* __restrict__ Bh, const __half* __restrict__ Bl,
    float* __restrict__ C, int M)
{
    extern __shared__ __half sh[];
    const int tid = threadIdx.x, lane = tid & 31, wid = tid >> 5;
    const int row0 = blockIdx.x * 128;
    const size_t slabE = (size_t)M * 128;
    const int STG = TILE_E + 2 * BTILE_E;

    float acc[6][4];
#pragma unroll
    for (int a = 0; a < 6; a++)
#pragma unroll
        for (int c = 0; c < 4; c++) acc[a][c] = 0.f;

    const int a_r = (lane & 7) + ((lane >> 3) & 1) * 8;
    const int a_c = (lane >> 4) * 8;
    const int b_r = (lane & 7) + (lane >> 4) * 8;
    const int b_c = ((lane >> 3) & 1) * 8;

    auto load_stage = [&](int st, int c) {
        const int k0g = c * 32;
        const int slab = 13 - (k0g >> 7);
        const int kin = k0g & 127;
        const __half* A = H16 + (size_t)slab * slabE;
        __half* sA = sh + st * STG;
        __half* sBh = sA + TILE_E;
        __half* sBl = sBh + BTILE_E;
#pragma unroll
        for (int i = tid; i < 512; i += 256) {
            int r = i >> 2, g = i & 3;
            uint32_t sz = (row0 + r < M) ? 16u : 0u;
            size_t go = (size_t)(row0 + r) * 128 + kin + g * 8;
            cp16(s2u(sA + r * LDK + g * 8), A + go, sz);
        }
        if (tid < 192) {
            int r = tid >> 2, g = tid & 3;
            size_t go = (size_t)r * 1792 + k0g + g * 8;
            cp16(s2u(sBh + r * LDK + g * 8), Bh + go, 16u);
            cp16(s2u(sBl + r * LDK + g * 8), Bl + go, 16u);
        }
        CP_COMMIT();
    };

    load_stage(0, 0);
    for (int c = 0; c < 56; c++) {
        if (c + 1 < 56) {
            load_stage((c + 1) & 1, c + 1);
            asm volatile("cp.async.wait_group 1;");
        } else {
            asm volatile("cp.async.wait_group 0;");
        }
        __syncthreads();

        const int st = c & 1;
        const __half* sA = sh + st * STG;
        const __half* sBh = sA + TILE_E;
        const __half* sBl = sBh + BTILE_E;
#pragma unroll
        for (int k16 = 0; k16 < 32; k16 += 16) {
            uint32_t a[4];
            int er = wid * 16 + a_r;
            int ec = k16 + a_c;
            ldsm4(a, s2u(sA + er * LDK + ec));
#pragma unroll
            for (int p = 0; p < 3; p++) {
                int br = p * 16 + b_r;
                int bc = k16 + b_c;
                uint32_t bh[4], bl[4];
                ldsm4(bh, s2u(sBh + br * LDK + bc));
                ldsm4(bl, s2u(sBl + br * LDK + bc));
                mma_fp16(acc[2 * p],     a, bh[0], bh[1]);
                mma_fp16(acc[2 * p],     a, bl[0], bl[1]);
                mma_fp16(acc[2 * p + 1], a, bh[2], bh[3]);
                mma_fp16(acc[2 * p + 1], a, bl[2], bl[3]);
            }
        }
        __syncthreads();
    }
    const int r1 = row0 + wid * 16 + (lane >> 2);
    const int r2 = r1 + 8;
#pragma unroll
    for (int nt = 0; nt < 5; nt++) {
        int col = nt * 8 + (lane & 3) * 2;
        if (r1 < M) *(float2*)(C + (size_t)r1 * 40 + col) =
            make_float2(acc[nt][0] * SLAB_UNSCALE, acc[nt][1] * SLAB_UNSCALE);
        if (r2 < M) *(float2*)(C + (size_t)r2 * 40 + col) =
            make_float2(acc[nt][2] * SLAB_UNSCALE, acc[nt][3] * SLAB_UNSCALE);
    }
}

// ---------------------------------------------------------------------------
// Final: agg40 + b15 + log_softmax. Warp per node. fp32 gather.
// ---------------------------------------------------------------------------
__global__ void __launch_bounds__(256) spmm40_lsm_kernel(
    const float* __restrict__ accum, const float* __restrict__ b15,
    float* __restrict__ out, int n)
{
    const int node = (blockIdx.x * blockDim.x + threadIdx.x) >> 5;
    if (node >= n) return;
    const int lane = threadIdx.x & 31;
    const int s = g_offs[node], e = g_offs[node + 1];

    float a1 = 0.f, a2 = 0.f;
    for (int i = s; i < e; i++) {
        int src = g_csr_src[i];
        float w = g_csr_w[i];
        const float* row = accum + (size_t)src * 40;
        a1 = fmaf(w, row[lane], a1);
        if (lane < 8) a2 = fmaf(w, row[32 + lane], a2);
    }
    float v1 = a1 + b15[lane];
    float v2 = (lane < 8) ? (a2 + b15[32 + lane]) : -3.0e38f;

    float m = fmaxf(v1, v2);
#pragma unroll
    for (int o = 16; o > 0; o >>= 1) m = fmaxf(m, __shfl_xor_sync(0xffffffffu, m, o));
    float sum = expf(v1 - m) + ((lane < 8) ? expf(v2 - m) : 0.f);
#pragma unroll
    for (int o = 16; o > 0; o >>= 1) sum += __shfl_xor_sync(0xffffffffu, sum, o);
    float ls = m + logf(sum);

    out[(size_t)node * 40 + lane] = v1 - ls;
    if (lane < 8) out[(size_t)node * 40 + 32 + lane] = v2 - ls;
}

// ---------------------------------------------------------------------------
// Launch
// ---------------------------------------------------------------------------
extern "C" void kernel_launch(void* const* d_in, const int* in_sizes, int n_in,
                              void* d_out, int out_size)
{
    const float* x    = (const float*)d_in[0];
    const int*   esrc = (const int*)  d_in[1];
    const int*   edst = (const int*)  d_in[2];
    const float* ew   = (const float*)d_in[3];
    const float* W0   = (const float*)d_in[4];
    const float* b0   = (const float*)d_in[5];
    const float* W1   = (const float*)d_in[6];
    const float* b1   = (const float*)d_in[7];
    const float* Wmid = (const float*)d_in[8];
    const float* bmid = (const float*)d_in[9];
    const float* W15  = (const float*)d_in[10];
    const float* b15  = (const float*)d_in[11];

    const int E = in_sizes[1];
    const int n = in_sizes[0] / 256;
    float* out = (float*)d_out;

    float *z, *h, *accum;
    __half *sup, *hf16, *wfh, *wfl;
    __nv_bfloat16 *wthi, *wtlo, *xhi, *xlo;
    cudaGetSymbolAddress((void**)&z,     g_z);
    cudaGetSymbolAddress((void**)&h,     g_h);
    cudaGetSymbolAddress((void**)&sup,   g_sup);
    cudaGetSymbolAddress((void**)&accum, g_acc);
    cudaGetSymbolAddress((void**)&wthi,  g_wthi);
    cudaGetSymbolAddress((void**)&wtlo,  g_wtlo);
    cudaGetSymbolAddress((void**)&wfh,   g_wfh);
    cudaGetSymbolAddress((void**)&wfl,   g_wfl);
    cudaGetSymbolAddress((void**)&xhi,   g_xhi);
    cudaGetSymbolAddress((void**)&xlo,   g_xlo);
    cudaGetSymbolAddress((void**)&hf16,  g_hf16);

    cudaFuncSetAttribute(tgemm_kernel<0>, cudaFuncAttributeMaxDynamicSharedMemorySize, SMEMSZ_G);
    cudaFuncSetAttribute(tgemm_kernel<1>, cudaFuncAttributeMaxDynamicSharedMemorySize, SMEMSZ_G);
    cudaFuncSetAttribute(tgemmf_kernel,   cudaFuncAttributeMaxDynamicSharedMemorySize, SMEMSZ_GF);
    cudaFuncSetAttribute(tgemm40f_kernel, cudaFuncAttributeMaxDynamicSharedMemorySize, SMEMSZ_G40F);

    const int TB = 256;
    const int gridE = (E + TB - 1) / TB;
    const int gridN = (n + TB - 1) / TB;
    const int gridT = (n + 127) / 128;
    const int gridSpmm = (n + 7) / 8;
    const size_t slab = (size_t)n * 128;

    // 1. CSR build + splits
    zero_deg_kernel<<<gridN, TB>>>(n);
    hist_kernel<<<gridE, TB>>>(edst, E);
    scan_kernel<<<1, 1024>>>(n);
    scatter_kernel<<<gridE, TB>>>(esrc, edst, ew, E);
    split_w_kernel<<<(WT_TOTAL + TB - 1) / TB, TB>>>(W0, W1, Wmid, W15);
    split_x_kernel<<<(n * 256 + TB - 1) / TB, TB>>>(x, n * 256);

    // 2. layer 1: z = x@W0+b0 ; sup = x@W1 (f16 2^-10) ; x1 -> h + slab0
    tgemm_kernel<0><<<gridT, 256, SMEMSZ_G>>>(xhi, xlo, wthi + WOFF_W0, wtlo + WOFF_W0, b0, z, n, 256);
    tgemm_kernel<1><<<gridT, 256, SMEMSZ_G>>>(xhi, xlo, wthi + WOFF_W1, wtlo + WOFF_W1, nullptr, sup, n, 256);
    spmm_relu_res_kernel<<<gridSpmm, 256>>>(sup, b1, z, h, hf16, n);

    // 3. mid layers: sup = slab_l @ Wmid[l] (fp16 GEMM) ; x_{l+1} -> h + slab_{l+1}
    for (int l = 0; l < 13; l++) {
        tgemmf_kernel<<<gridT, 256, SMEMSZ_GF>>>(hf16 + (size_t)l * slab,
                                                 wfh + WOFF_MID + (size_t)l * 16384,
                                                 wfl + WOFF_MID + (size_t)l * 16384,
                                                 sup, n);
        spmm_relu_res_kernel<<<gridSpmm, 256>>>(sup, bmid + (size_t)l * 128, h, h,
                                                hf16 + (size_t)(l + 1) * slab, n);
    }

    // 4. P = X_cat @ W15 (fp16 path over f16 slabs)
    tgemm40f_kernel<<<gridT, 256, SMEMSZ_G40F>>>(hf16, wfh + WOFF_W15, wfl + WOFF_W15, accum, n);

    // 5. out = log_softmax(agg40(P) + b15)
    spmm40_lsm_kernel<<<gridSpmm, 256>>>(accum, b15, out, n);
}

// round 11
// speedup vs baseline: 2.3335x; 1.0698x over previous
#include <cuda_runtime.h>
#include <cuda_bf16.h>
#include <cuda_fp16.h>
#include <math.h>
#include <stdint.h>

// ---------------------------------------------------------------------------
// ResGCN15 (sm_103 -> HMMA mma.sync).
// R10 structure with SINGLE-f16 weights in mid + final GEMMs (W-lo dropped;
// ~1e-4/layer perturbation, quadrature-safe). Layer-1 keeps bf16 hi/lo split.
//  - activations: scaled f16 slabs (2^-15) feed mid GEMMs + final GEMM
//  - residual path fp32 h (exact)
//  - sup stream f16 (2^-10)
// ---------------------------------------------------------------------------

#define MAX_N 50000
#define MAX_E 800000
#define NHID 128
#define NCLASS 40
#define LDK 40          // smem row stride (32 elems + 8 pad)

#define SUP_SCALE    0.0009765625f      // 2^-10 (sup stream)
#define SUP_UNSCALE  1024.0f
#define SLAB_SCALE   0.000030517578125f // 2^-15 (activation slabs)
#define SLAB_UNSCALE 32768.0f
#define ACC2SUP      32.0f              // 2^15 * 2^-10

#define WOFF_W0   0
#define WOFF_W1   32768
#define WOFF_MID  65536
#define WOFF_W15  278528
#define WT_TOTAL  364544

__device__ __align__(16) int   g_deg[MAX_N];
__device__ __align__(16) int   g_offs[MAX_N + 1];
__device__ __align__(16) int   g_cursor[MAX_N];
__device__ __align__(16) int   g_csr_src[MAX_E];
__device__ __align__(16) float g_csr_w[MAX_E];
__device__ __align__(16) float g_z[(size_t)MAX_N * NHID];
__device__ __align__(16) float g_h[(size_t)MAX_N * NHID];
__device__ __align__(16) __half g_sup[(size_t)MAX_N * NHID];
__device__ __align__(16) float g_acc[(size_t)MAX_N * NCLASS];
__device__ __align__(16) __nv_bfloat16 g_wthi[WT_TOTAL];
__device__ __align__(16) __nv_bfloat16 g_wtlo[WT_TOTAL];
__device__ __align__(16) __half g_wfh[WT_TOTAL];
__device__ __align__(16) __nv_bfloat16 g_xhi[(size_t)MAX_N * 256];
__device__ __align__(16) __nv_bfloat16 g_xlo[(size_t)MAX_N * 256];
__device__ __align__(16) __half g_hf16[(size_t)14 * MAX_N * NHID];  // 2^-15

// ---------------------------------------------------------------------------
// helpers
// ---------------------------------------------------------------------------
__device__ __forceinline__ uint32_t s2u(const void* p) {
    return (uint32_t)__cvta_generic_to_shared(p);
}
__device__ __forceinline__ void ldsm4(uint32_t* r, uint32_t addr) {
    asm volatile("ldmatrix.sync.aligned.m8n8.x4.shared.b16 {%0,%1,%2,%3}, [%4];"
                 : "=r"(r[0]), "=r"(r[1]), "=r"(r[2]), "=r"(r[3]) : "r"(addr));
}
__device__ __forceinline__ void mma_bf16(float* d, const uint32_t* a,
                                         uint32_t b0, uint32_t b1) {
    asm volatile(
        "mma.sync.aligned.m16n8k16.row.col.f32.bf16.bf16.f32 "
        "{%0,%1,%2,%3}, {%4,%5,%6,%7}, {%8,%9}, {%0,%1,%2,%3};"
        : "+f"(d[0]), "+f"(d[1]), "+f"(d[2]), "+f"(d[3])
        : "r"(a[0]), "r"(a[1]), "r"(a[2]), "r"(a[3]), "r"(b0), "r"(b1));
}
__device__ __forceinline__ void mma_fp16(float* d, const uint32_t* a,
                                         uint32_t b0, uint32_t b1) {
    asm volatile(
        "mma.sync.aligned.m16n8k16.row.col.f32.f16.f16.f32 "
        "{%0,%1,%2,%3}, {%4,%5,%6,%7}, {%8,%9}, {%0,%1,%2,%3};"
        : "+f"(d[0]), "+f"(d[1]), "+f"(d[2]), "+f"(d[3])
        : "r"(a[0]), "r"(a[1]), "r"(a[2]), "r"(a[3]), "r"(b0), "r"(b1));
}
__device__ __forceinline__ void split1(float v, __nv_bfloat16& h, __nv_bfloat16& l) {
    h = __float2bfloat16(v);
    l = __float2bfloat16(v - __bfloat162float(h));
}
__device__ __forceinline__ void cp16(uint32_t saddr, const void* gptr, uint32_t sz) {
    asm volatile("cp.async.cg.shared.global [%0], [%1], 16, %2;"
                 :: "r"(saddr), "l"(gptr), "r"(sz));
}
#define CP_COMMIT() asm volatile("cp.async.commit_group;")

// ---------------------------------------------------------------------------
// CSR build
// ---------------------------------------------------------------------------
__global__ void zero_deg_kernel(int n) {
    int i = blockIdx.x * blockDim.x + threadIdx.x;
    if (i < n) g_deg[i] = 0;
}
__global__ void hist_kernel(const int* __restrict__ dst, int E) {
    int i = blockIdx.x * blockDim.x + threadIdx.x;
    if (i < E) atomicAdd(&g_deg[dst[i]], 1);
}
__global__ void scan_kernel(int n) {
    __shared__ int sums[1024];
    const int t = threadIdx.x;
    const int chunk = (n + 1023) >> 10;
    const int begin = t * chunk;
    const int end = min(begin + chunk, n);
    int s = 0;
    for (int i = begin; i < end; i++) s += g_deg[i];
    sums[t] = s;
    __syncthreads();
    for (int d = 1; d < 1024; d <<= 1) {
        int v = (t >= d) ? sums[t - d] : 0;
        __syncthreads();
        sums[t] += v;
        __syncthreads();
    }
    int run = (t == 0) ? 0 : sums[t - 1];
    if (t == 0) g_offs[0] = 0;
    for (int i = begin; i < end; i++) {
        g_cursor[i] = run;
        run += g_deg[i];
        g_offs[i + 1] = run;
    }
}
__global__ void scatter_kernel(const int* __restrict__ src, const int* __restrict__ dst,
                               const float* __restrict__ w, int E) {
    int i = blockIdx.x * blockDim.x + threadIdx.x;
    if (i < E) {
        int d = dst[i];
        int pos = atomicAdd(&g_cursor[d], 1);
        g_csr_src[pos] = src[i];
        g_csr_w[pos] = w[i];
    }
}

// ---------------------------------------------------------------------------
// prep: weights transposed; bf16 hi/lo (layer-1) + single f16 (mid + W15)
// ---------------------------------------------------------------------------
__global__ void split_w_kernel(const float* __restrict__ W0, const float* __restrict__ W1,
                               const float* __restrict__ Wmid, const float* __restrict__ W15) {
    int i = blockIdx.x * blockDim.x + threadIdx.x;
    if (i >= WT_TOTAL) return;
    float v;
    if (i < 32768) {
        int n = i >> 8, k = i & 255;
        v = W0[k * 128 + n];
    } else if (i < 65536) {
        int j = i - 32768;
        int n = j >> 8, k = j & 255;
        v = W1[k * 128 + n];
    } else if (i < 278528) {
        int j = i - 65536;
        int l = j >> 14, jj = j & 16383;
        int n = jj >> 7, k = jj & 127;
        v = Wmid[l * 16384 + k * 128 + n];
    } else {
        int j = i - 278528;
        int n = j / 1792, k = j % 1792;
        v = (n < 40) ? W15[(size_t)k * 40 + n] : 0.f;
    }
    __nv_bfloat16 h, l;
    split1(v, h, l);
    g_wthi[i] = h;
    g_wtlo[i] = l;
    g_wfh[i] = __float2half_rn(v);
}
__global__ void split_x_kernel(const float* __restrict__ x, int total) {
    int i = blockIdx.x * blockDim.x + threadIdx.x;
    if (i >= total) return;
    __nv_bfloat16 h, l;
    split1(x[i], h, l);
    g_xhi[i] = h;
    g_xlo[i] = l;
}

// ---------------------------------------------------------------------------
// Pipelined bf16-split GEMM (layer 1): C[M,128] = A[M,K] @ Bt[128,K]^T.
// OUTF16=0: fp32 out (+bias). OUTF16=1: f16 out scaled 2^-10 (no bias).
// ---------------------------------------------------------------------------
#define TILE_E (128 * LDK)
#define SMEMSZ_G (2 * 4 * TILE_E * 2)

template<int OUTF16>
__global__ void __launch_bounds__(256) tgemm_kernel(
    const __nv_bfloat16* __restrict__ Ahi, const __nv_bfloat16* __restrict__ Alo,
    const __nv_bfloat16* __restrict__ Bhi, const __nv_bfloat16* __restrict__ Blo,
    const float* __restrict__ bias, void* __restrict__ Cout, int M, int K)
{
    extern __shared__ __nv_bfloat16 sb[];
    const int tid = threadIdx.x, lane = tid & 31, wid = tid >> 5;
    const int row0 = blockIdx.x * 128;
    const int wm = wid & 3, wn = wid >> 2;

    float acc[2][8][4];
#pragma unroll
    for (int a = 0; a < 2; a++)
#pragma unroll
        for (int b = 0; b < 8; b++)
#pragma unroll
            for (int c = 0; c < 4; c++) acc[a][b][c] = 0.f;

    const int a_r = (lane & 7) + ((lane >> 3) & 1) * 8;
    const int a_c = (lane >> 4) * 8;
    const int b_r = (lane & 7) + (lane >> 4) * 8;
    const int b_c = ((lane >> 3) & 1) * 8;
    const int nc = K >> 5;

    auto load_stage = [&](int st, int k0) {
        __nv_bfloat16* sAh = sb + (st * 4 + 0) * TILE_E;
        __nv_bfloat16* sAl = sb + (st * 4 + 1) * TILE_E;
        __nv_bfloat16* sBh = sb + (st * 4 + 2) * TILE_E;
        __nv_bfloat16* sBl = sb + (st * 4 + 3) * TILE_E;
#pragma unroll
        for (int i = tid; i < 512; i += 256) {
            int r = i >> 2, g = i & 3;
            uint32_t sz = (row0 + r < M) ? 16u : 0u;
            size_t go = (size_t)(row0 + r) * K + k0 + g * 8;
            cp16(s2u(sAh + r * LDK + g * 8), Ahi + go, sz);
            cp16(s2u(sAl + r * LDK + g * 8), Alo + go, sz);
        }
#pragma unroll
        for (int i = tid; i < 512; i += 256) {
            int r = i >> 2, g = i & 3;
            size_t go = (size_t)r * K + k0 + g * 8;
            cp16(s2u(sBh + r * LDK + g * 8), Bhi + go, 16u);
            cp16(s2u(sBl + r * LDK + g * 8), Blo + go, 16u);
        }
        CP_COMMIT();
    };

    load_stage(0, 0);
    for (int c = 0; c < nc; c++) {
        if (c + 1 < nc) {
            load_stage((c + 1) & 1, (c + 1) << 5);
            asm volatile("cp.async.wait_group 1;");
        } else {
            asm volatile("cp.async.wait_group 0;");
        }
        __syncthreads();

        const int st = c & 1;
        const __nv_bfloat16* sAh = sb + (st * 4 + 0) * TILE_E;
        const __nv_bfloat16* sAl = sb + (st * 4 + 1) * TILE_E;
        const __nv_bfloat16* sBh = sb + (st * 4 + 2) * TILE_E;
        const __nv_bfloat16* sBl = sb + (st * 4 + 3) * TILE_E;
#pragma unroll
        for (int k16 = 0; k16 < 32; k16 += 16) {
            uint32_t ah[2][4], al[2][4];
#pragma unroll
            for (int mt = 0; mt < 2; mt++) {
                int er = wm * 32 + mt * 16 + a_r;
                int ec = k16 + a_c;
                ldsm4(ah[mt], s2u(sAh + er * LDK + ec));
                ldsm4(al[mt], s2u(sAl + er * LDK + ec));
            }
#pragma unroll
            for (int p = 0; p < 4; p++) {
                int er = wn * 64 + p * 16 + b_r;
                int ec = k16 + b_c;
                uint32_t bh[4], bl[4];
                ldsm4(bh, s2u(sBh + er * LDK + ec));
                ldsm4(bl, s2u(sBl + er * LDK + ec));
#pragma unroll
                for (int mt = 0; mt < 2; mt++) {
                    mma_bf16(acc[mt][2 * p],     ah[mt], bh[0], bh[1]);
                    mma_bf16(acc[mt][2 * p],     ah[mt], bl[0], bl[1]);
                    mma_bf16(acc[mt][2 * p],     al[mt], bh[0], bh[1]);
                    mma_bf16(acc[mt][2 * p + 1], ah[mt], bh[2], bh[3]);
                    mma_bf16(acc[mt][2 * p + 1], ah[mt], bl[2], bl[3]);
                    mma_bf16(acc[mt][2 * p + 1], al[mt], bh[2], bh[3]);
                }
            }
        }
        __syncthreads();
    }

    const int er0 = row0 + wm * 32 + (lane >> 2);
    const int ec0 = wn * 64 + (lane & 3) * 2;
#pragma unroll
    for (int mt = 0; mt < 2; mt++) {
#pragma unroll
        for (int nt = 0; nt < 8; nt++) {
            int col = ec0 + nt * 8;
            float bx = 0.f, by = 0.f;
            if (!OUTF16 && bias) { bx = bias[col]; by = bias[col + 1]; }
            int r1 = er0 + mt * 16, r2 = r1 + 8;
#pragma unroll
            for (int half = 0; half < 2; half++) {
                int r = half ? r2 : r1;
                if (r >= M) continue;
                float vx = acc[mt][nt][half * 2] + bx;
                float vy = acc[mt][nt][half * 2 + 1] + by;
                if (OUTF16) {
                    __half2* C = (__half2*)Cout;
                    C[((size_t)r * 128 + col) >> 1] =
                        __floats2half2_rn(vx * SUP_SCALE, vy * SUP_SCALE);
                } else {
                    float* C = (float*)Cout;
                    *(float2*)(C + (size_t)r * 128 + col) = make_float2(vx, vy);
                }
            }
        }
    }
}

// ---------------------------------------------------------------------------
// Mid-layer fp16 GEMM: sup = x_l @ W.  A = f16 slab (2^-15), B = W single f16.
// Output sup f16 scaled 2^-10 (acc * 2^5).  1 fp16 MMA per (a-frag, col-pair).
// ---------------------------------------------------------------------------
#define SMEMSZ_GF (2 * 2 * TILE_E * 2)

__global__ void __launch_bounds__(256) tgemmf_kernel(
    const __half* __restrict__ A16, const __half* __restrict__ B16,
    __half* __restrict__ Cout, int M)
{
    extern __shared__ __half sh[];
    const int tid = threadIdx.x, lane = tid & 31, wid = tid >> 5;
    const int row0 = blockIdx.x * 128;
    const int wm = wid & 3, wn = wid >> 2;

    float acc[2][8][4];
#pragma unroll
    for (int a = 0; a < 2; a++)
#pragma unroll
        for (int b = 0; b < 8; b++)
#pragma unroll
            for (int c = 0; c < 4; c++) acc[a][b][c] = 0.f;

    const int a_r = (lane & 7) + ((lane >> 3) & 1) * 8;
    const int a_c = (lane >> 4) * 8;
    const int b_r = (lane & 7) + (lane >> 4) * 8;
    const int b_c = ((lane >> 3) & 1) * 8;

    auto load_stage = [&](int st, int k0) {
        __half* sA = sh + st * 2 * TILE_E;
        __half* sB = sA + TILE_E;
#pragma unroll
        for (int i = tid; i < 512; i += 256) {
            int r = i >> 2, g = i & 3;
            uint32_t sz = (row0 + r < M) ? 16u : 0u;
            size_t go = (size_t)(row0 + r) * 128 + k0 + g * 8;
            cp16(s2u(sA + r * LDK + g * 8), A16 + go, sz);
        }
#pragma unroll
        for (int i = tid; i < 512; i += 256) {
            int r = i >> 2, g = i & 3;
            size_t go = (size_t)r * 128 + k0 + g * 8;
            cp16(s2u(sB + r * LDK + g * 8), B16 + go, 16u);
        }
        CP_COMMIT();
    };

    load_stage(0, 0);
    for (int c = 0; c < 4; c++) {
        if (c + 1 < 4) {
            load_stage((c + 1) & 1, (c + 1) << 5);
            asm volatile("cp.async.wait_group 1;");
        } else {
            asm volatile("cp.async.wait_group 0;");
        }
        __syncthreads();

        const int st = c & 1;
        const __half* sA = sh + st * 2 * TILE_E;
        const __half* sB = sA + TILE_E;
#pragma unroll
        for (int k16 = 0; k16 < 32; k16 += 16) {
            uint32_t a[2][4];
#pragma unroll
            for (int mt = 0; mt < 2; mt++) {
                int er = wm * 32 + mt * 16 + a_r;
                int ec = k16 + a_c;
                ldsm4(a[mt], s2u(sA + er * LDK + ec));
            }
#pragma unroll
            for (int p = 0; p < 4; p++) {
                int er = wn * 64 + p * 16 + b_r;
                int ec = k16 + b_c;
                uint32_t b[4];
                ldsm4(b, s2u(sB + er * LDK + ec));
#pragma unroll
                for (int mt = 0; mt < 2; mt++) {
                    mma_fp16(acc[mt][2 * p],     a[mt], b[0], b[1]);
                    mma_fp16(acc[mt][2 * p + 1], a[mt], b[2], b[3]);
                }
            }
        }
        __syncthreads();
    }

    const int er0 = row0 + wm * 32 + (lane >> 2);
    const int ec0 = wn * 64 + (lane & 3) * 2;
#pragma unroll
    for (int mt = 0; mt < 2; mt++) {
#pragma unroll
        for (int nt = 0; nt < 8; nt++) {
            int col = ec0 + nt * 8;
            int r1 = er0 + mt * 16, r2 = r1 + 8;
#pragma unroll
            for (int half = 0; half < 2; half++) {
                int r = half ? r2 : r1;
                if (r >= M) continue;
                float vx = acc[mt][nt][half * 2] * ACC2SUP;
                float vy = acc[mt][nt][half * 2 + 1] * ACC2SUP;
                ((__half2*)Cout)[((size_t)r * 128 + col) >> 1] =
                    __floats2half2_rn(vx, vy);
            }
        }
    }
}

// ---------------------------------------------------------------------------
// SpMM d=128: warp per node, f16 sup gather (2^-10).
// out = relu(agg*2^10 + bias) + res (fp32) ; also writes f16 slab (2^-15).
// res may alias out.
// ---------------------------------------------------------------------------
__global__ void __launch_bounds__(256) spmm_relu_res_kernel(
    const __half* __restrict__ support, const float* __restrict__ bias,
    const float* __restrict__ res, float* __restrict__ out,
    __half* __restrict__ out16, int n)
{
    const int node = (blockIdx.x * blockDim.x + threadIdx.x) >> 5;
    if (node >= n) return;
    const int lane = threadIdx.x & 31;
    const int s = g_offs[node], e = g_offs[node + 1];
    const uint2* sup2 = (const uint2*)support;

    float4 acc = make_float4(0.f, 0.f, 0.f, 0.f);
    int i = s;
    for (; i + 1 < e; i += 2) {
        int s0 = g_csr_src[i], s1 = g_csr_src[i + 1];
        float w0 = g_csr_w[i],  w1 = g_csr_w[i + 1];
        uint2 u0 = sup2[(size_t)s0 * 32 + lane];
        uint2 u1 = sup2[(size_t)s1 * 32 + lane];
        float2 a0 = __half22float2(*(const __half2*)&u0.x);
        float2 a1 = __half22float2(*(const __half2*)&u0.y);
        acc.x = fmaf(w0, a0.x, acc.x); acc.y = fmaf(w0, a0.y, acc.y);
        acc.z = fmaf(w0, a1.x, acc.z); acc.w = fmaf(w0, a1.y, acc.w);
        float2 b0 = __half22float2(*(const __half2*)&u1.x);
        float2 b1 = __half22float2(*(const __half2*)&u1.y);
        acc.x = fmaf(w1, b0.x, acc.x); acc.y = fmaf(w1, b0.y, acc.y);
        acc.z = fmaf(w1, b1.x, acc.z); acc.w = fmaf(w1, b1.y, acc.w);
    }
    if (i < e) {
        int s0 = g_csr_src[i];
        float w0 = g_csr_w[i];
        uint2 u0 = sup2[(size_t)s0 * 32 + lane];
        float2 a0 = __half22float2(*(const __half2*)&u0.x);
        float2 a1 = __half22float2(*(const __half2*)&u0.y);
        acc.x = fmaf(w0, a0.x, acc.x); acc.y = fmaf(w0, a0.y, acc.y);
        acc.z = fmaf(w0, a1.x, acc.z); acc.w = fmaf(w0, a1.y, acc.w);
    }
    acc.x *= SUP_UNSCALE; acc.y *= SUP_UNSCALE;
    acc.z *= SUP_UNSCALE; acc.w *= SUP_UNSCALE;

    float4 b = ((const float4*)bias)[lane];
    float4 r = ((const float4*)res)[(size_t)node * 32 + lane];
    float4 o;
    o.x = fmaxf(acc.x + b.x, 0.f) + r.x;
    o.y = fmaxf(acc.y + b.y, 0.f) + r.y;
    o.z = fmaxf(acc.z + b.z, 0.f) + r.z;
    o.w = fmaxf(acc.w + b.w, 0.f) + r.w;
    ((float4*)out)[(size_t)node * 32 + lane] = o;

    uint2 w16;
    __half2 f0 = __floats2half2_rn(o.x * SLAB_SCALE, o.y * SLAB_SCALE);
    __half2 f1 = __floats2half2_rn(o.z * SLAB_SCALE, o.w * SLAB_SCALE);
    w16.x = *(uint32_t*)&f0;
    w16.y = *(uint32_t*)&f1;
    ((uint2*)(out16 + (size_t)node * 128))[lane] = w16;
}

// ---------------------------------------------------------------------------
// Final GEMM (fp16): C[M,40] = X_cat(f16, 2^-15)[M,1792] @ W15f[48,1792]^T * 2^15
// Single-f16 W15.
// ---------------------------------------------------------------------------
#define BTILE_E (48 * LDK)
#define SMEMSZ_G40F (2 * (TILE_E + BTILE_E) * 2)

__global__ void __launch_bounds__(256) tgemm40f_kernel(
    const __half* __restrict__ H16, const __half* __restrict__ B16,
    float* __restrict__ C, int M)
{
    extern __shared__ __half sh[];
    const int tid = threadIdx.x, lane = tid & 31, wid = tid >> 5;
    const int row0 = blockIdx.x * 128;
    const size_t slabE = (size_t)M * 128;
    const int STG = TILE_E + BTILE_E;

    float acc[6][4];
#pragma unroll
    for (int a = 0; a < 6; a++)
#pragma unroll
        for (int c = 0; c < 4; c++) acc[a][c] = 0.f;

    const int a_r = (lane & 7) + ((lane >> 3) & 1) * 8;
    const int a_c = (lane >> 4) * 8;
    const int b_r = (lane & 7) + (lane >> 4) * 8;
    const int b_c = ((lane >> 3) & 1) * 8;

    auto load_stage = [&](int st, int c) {
        const int k0g = c * 32;
        const int slab = 13 - (k0g >> 7);
        const int kin = k0g & 127;
        const __half* A = H16 + (size_t)slab * slabE;
        __half* sA = sh + st * STG;
        __half* sB = sA + TILE_E;
#pragma unroll
        for (int i = tid; i < 512; i += 256) {
            int r = i >> 2, g = i & 3;
            uint32_t sz = (row0 + r < M) ? 16u : 0u;
            size_t go = (size_t)(row0 + r) * 128 + kin + g * 8;
            cp16(s2u(sA + r * LDK + g * 8), A + go, sz);
        }
        if (tid < 192) {
            int r = tid >> 2, g = tid & 3;
            size_t go = (size_t)r * 1792 + k0g + g * 8;
            cp16(s2u(sB + r * LDK + g * 8), B16 + go, 16u);
        }
        CP_COMMIT();
    };

    load_stage(0, 0);
    for (int c = 0; c < 56; c++) {
        if (c + 1 < 56) {
            load_stage((c + 1) & 1, c + 1);
            asm volatile("cp.async.wait_group 1;");
        } else {
            asm volatile("cp.async.wait_group 0;");
        }
        __syncthreads();

        const int st = c & 1;
        const __half* sA = sh + st * STG;
        const __half* sB = sA + TILE_E;
#pragma unroll
        for (int k16 = 0; k16 < 32; k16 += 16) {
            uint32_t a[4];
            int er = wid * 16 + a_r;
            int ec = k16 + a_c;
            ldsm4(a, s2u(sA + er * LDK + ec));
#pragma unroll
            for (int p = 0; p < 3; p++) {
                int br = p * 16 + b_r;
                int bc = k16 + b_c;
                uint32_t b[4];
                ldsm4(b, s2u(sB + br * LDK + bc));
                mma_fp16(acc[2 * p],     a, b[0], b[1]);
                mma_fp16(acc[2 * p + 1], a, b[2], b[3]);
            }
        }
        __syncthreads();
    }
    const int r1 = row0 + wid * 16 + (lane >> 2);
    const int r2 = r1 + 8;
#pragma unroll
    for (int nt = 0; nt < 5; nt++) {
        int col = nt * 8 + (lane & 3) * 2;
        if (r1 < M) *(float2*)(C + (size_t)r1 * 40 + col) =
            make_float2(acc[nt][0] * SLAB_UNSCALE, acc[nt][1] * SLAB_UNSCALE);
        if (r2 < M) *(float2*)(C + (size_t)r2 * 40 + col) =
            make_float2(acc[nt][2] * SLAB_UNSCALE, acc[nt][3] * SLAB_UNSCALE);
    }
}

// ---------------------------------------------------------------------------
// Final: agg40 + b15 + log_softmax. Warp per node. fp32 gather.
// ---------------------------------------------------------------------------
__global__ void __launch_bounds__(256) spmm40_lsm_kernel(
    const float* __restrict__ accum, const float* __restrict__ b15,
    float* __restrict__ out, int n)
{
    const int node = (blockIdx.x * blockDim.x + threadIdx.x) >> 5;
    if (node >= n) return;
    const int lane = threadIdx.x & 31;
    const int s = g_offs[node], e = g_offs[node + 1];

    float a1 = 0.f, a2 = 0.f;
    for (int i = s; i < e; i++) {
        int src = g_csr_src[i];
        float w = g_csr_w[i];
        const float* row = accum + (size_t)src * 40;
        a1 = fmaf(w, row[lane], a1);
        if (lane < 8) a2 = fmaf(w, row[32 + lane], a2);
    }
    float v1 = a1 + b15[lane];
    float v2 = (lane < 8) ? (a2 + b15[32 + lane]) : -3.0e38f;

    float m = fmaxf(v1, v2);
#pragma unroll
    for (int o = 16; o > 0; o >>= 1) m = fmaxf(m, __shfl_xor_sync(0xffffffffu, m, o));
    float sum = expf(v1 - m) + ((lane < 8) ? expf(v2 - m) : 0.f);
#pragma unroll
    for (int o = 16; o > 0; o >>= 1) sum += __shfl_xor_sync(0xffffffffu, sum, o);
    float ls = m + logf(sum);

    out[(size_t)node * 40 + lane] = v1 - ls;
    if (lane < 8) out[(size_t)node * 40 + 32 + lane] = v2 - ls;
}

// ---------------------------------------------------------------------------
// Launch
// ---------------------------------------------------------------------------
extern "C" void kernel_launch(void* const* d_in, const int* in_sizes, int n_in,
                              void* d_out, int out_size)
{
    const float* x    = (const float*)d_in[0];
    const int*   esrc = (const int*)  d_in[1];
    const int*   edst = (const int*)  d_in[2];
    const float* ew   = (const float*)d_in[3];
    const float* W0   = (const float*)d_in[4];
    const float* b0   = (const float*)d_in[5];
    const float* W1   = (const float*)d_in[6];
    const float* b1   = (const float*)d_in[7];
    const float* Wmid = (const float*)d_in[8];
    const float* bmid = (const float*)d_in[9];
    const float* W15  = (const float*)d_in[10];
    const float* b15  = (const float*)d_in[11];

    const int E = in_sizes[1];
    const int n = in_sizes[0] / 256;
    float* out = (float*)d_out;

    float *z, *h, *accum;
    __half *sup, *hf16, *wfh;
    __nv_bfloat16 *wthi, *wtlo, *xhi, *xlo;
    cudaGetSymbolAddress((void**)&z,     g_z);
    cudaGetSymbolAddress((void**)&h,     g_h);
    cudaGetSymbolAddress((void**)&sup,   g_sup);
    cudaGetSymbolAddress((void**)&accum, g_acc);
    cudaGetSymbolAddress((void**)&wthi,  g_wthi);
    cudaGetSymbolAddress((void**)&wtlo,  g_wtlo);
    cudaGetSymbolAddress((void**)&wfh,   g_wfh);
    cudaGetSymbolAddress((void**)&xhi,   g_xhi);
    cudaGetSymbolAddress((void**)&xlo,   g_xlo);
    cudaGetSymbolAddress((void**)&hf16,  g_hf16);

    cudaFuncSetAttribute(tgemm_kernel<0>, cudaFuncAttributeMaxDynamicSharedMemorySize, SMEMSZ_G);
    cudaFuncSetAttribute(tgemm_kernel<1>, cudaFuncAttributeMaxDynamicSharedMemorySize, SMEMSZ_G);
    cudaFuncSetAttribute(tgemmf_kernel,   cudaFuncAttributeMaxDynamicSharedMemorySize, SMEMSZ_GF);
    cudaFuncSetAttribute(tgemm40f_kernel, cudaFuncAttributeMaxDynamicSharedMemorySize, SMEMSZ_G40F);

    const int TB = 256;
    const int gridE = (E + TB - 1) / TB;
    const int gridN = (n + TB - 1) / TB;
    const int gridT = (n + 127) / 128;
    const int gridSpmm = (n + 7) / 8;
    const size_t slab = (size_t)n * 128;

    // 1. CSR build + splits
    zero_deg_kernel<<<gridN, TB>>>(n);
    hist_kernel<<<gridE, TB>>>(edst, E);
    scan_kernel<<<1, 1024>>>(n);
    scatter_kernel<<<gridE, TB>>>(esrc, edst, ew, E);
    split_w_kernel<<<(WT_TOTAL + TB - 1) / TB, TB>>>(W0, W1, Wmid, W15);
    split_x_kernel<<<(n * 256 + TB - 1) / TB, TB>>>(x, n * 256);

    // 2. layer 1: z = x@W0+b0 ; sup = x@W1 (f16 2^-10) ; x1 -> h + slab0
    tgemm_kernel<0><<<gridT, 256, SMEMSZ_G>>>(xhi, xlo, wthi + WOFF_W0, wtlo + WOFF_W0, b0, z, n, 256);
    tgemm_kernel<1><<<gridT, 256, SMEMSZ_G>>>(xhi, xlo, wthi + WOFF_W1, wtlo + WOFF_W1, nullptr, sup, n, 256);
    spmm_relu_res_kernel<<<gridSpmm, 256>>>(sup, b1, z, h, hf16, n);

    // 3. mid layers: sup = slab_l @ Wmid[l] (fp16 GEMM) ; x_{l+1} -> h + slab_{l+1}
    for (int l = 0; l < 13; l++) {
        tgemmf_kernel<<<gridT, 256, SMEMSZ_GF>>>(hf16 + (size_t)l * slab,
                                                 wfh + WOFF_MID + (size_t)l * 16384,
                                                 sup, n);
        spmm_relu_res_kernel<<<gridSpmm, 256>>>(sup, bmid + (size_t)l * 128, h, h,
                                                hf16 + (size_t)(l + 1) * slab, n);
    }

    // 4. P = X_cat @ W15 (fp16 path over f16 slabs, single-f16 W15)
    tgemm40f_kernel<<<gridT, 256, SMEMSZ_G40F>>>(hf16, wfh + WOFF_W15, accum, n);

    // 5. out = log_softmax(agg40(P) + b15)
    spmm40_lsm_kernel<<<gridSpmm, 256>>>(accum, b15, out, n);
}

// round 12
// speedup vs baseline: 2.5003x; 1.0715x over previous
#include <cuda_runtime.h>
#include <cuda_fp16.h>
#include <math.h>
#include <stdint.h>

// ---------------------------------------------------------------------------
// ResGCN15 (sm_103 -> HMMA fp16 mma.sync everywhere).
// All activations live in scaled f16 slabs (2^-15) which ALSO carry the
// residual (fp32 h dropped; growth makes early roundings negligible).
// All weights single f16 (transposed). sup stream f16 (2^-10).
//   layer1: z = x@W0+b0 (fp32 out) ; sup = x@W1 ; slab0 = relu(agg+b1)+z
//   mid l : sup = slab_l@W (fp16 GEMM) ; slab_{l+1} = relu(agg+b)+slab_l*2^15
//   final : P = X_cat@W15 over 14 slabs ; out = lsm(agg40(P)+b15)
// ---------------------------------------------------------------------------

#define MAX_N 50000
#define MAX_E 800000
#define NHID 128
#define NCLASS 40
#define LDK 40          // smem row stride (32 elems + 8 pad)

#define SUP_SCALE    0.0009765625f      // 2^-10 (sup stream)
#define SUP_UNSCALE  1024.0f
#define SLAB_SCALE   0.000030517578125f // 2^-15 (activation slabs)
#define SLAB_UNSCALE 32768.0f
#define ACC2SUP      32.0f              // 2^15 * 2^-10

#define WOFF_W0   0
#define WOFF_W1   32768
#define WOFF_MID  65536
#define WOFF_W15  278528
#define WT_TOTAL  364544

__device__ __align__(16) int   g_deg[MAX_N];
__device__ __align__(16) int   g_offs[MAX_N + 1];
__device__ __align__(16) int   g_cursor[MAX_N];
__device__ __align__(16) int   g_csr_src[MAX_E];
__device__ __align__(16) float g_csr_w[MAX_E];
__device__ __align__(16) float g_z[(size_t)MAX_N * NHID];
__device__ __align__(16) __half g_sup[(size_t)MAX_N * NHID];
__device__ __align__(16) float g_acc[(size_t)MAX_N * NCLASS];
__device__ __align__(16) __half g_wfh[WT_TOTAL];
__device__ __align__(16) __half g_xf16[(size_t)MAX_N * 256];
__device__ __align__(16) __half g_hf16[(size_t)14 * MAX_N * NHID];  // 2^-15

// ---------------------------------------------------------------------------
// helpers
// ---------------------------------------------------------------------------
__device__ __forceinline__ uint32_t s2u(const void* p) {
    return (uint32_t)__cvta_generic_to_shared(p);
}
__device__ __forceinline__ void ldsm4(uint32_t* r, uint32_t addr) {
    asm volatile("ldmatrix.sync.aligned.m8n8.x4.shared.b16 {%0,%1,%2,%3}, [%4];"
                 : "=r"(r[0]), "=r"(r[1]), "=r"(r[2]), "=r"(r[3]) : "r"(addr));
}
__device__ __forceinline__ void mma_fp16(float* d, const uint32_t* a,
                                         uint32_t b0, uint32_t b1) {
    asm volatile(
        "mma.sync.aligned.m16n8k16.row.col.f32.f16.f16.f32 "
        "{%0,%1,%2,%3}, {%4,%5,%6,%7}, {%8,%9}, {%0,%1,%2,%3};"
        : "+f"(d[0]), "+f"(d[1]), "+f"(d[2]), "+f"(d[3])
        : "r"(a[0]), "r"(a[1]), "r"(a[2]), "r"(a[3]), "r"(b0), "r"(b1));
}
__device__ __forceinline__ void cp16(uint32_t saddr, const void* gptr, uint32_t sz) {
    asm volatile("cp.async.cg.shared.global [%0], [%1], 16, %2;"
                 :: "r"(saddr), "l"(gptr), "r"(sz));
}
#define CP_COMMIT() asm volatile("cp.async.commit_group;")

// ---------------------------------------------------------------------------
// CSR build
// ---------------------------------------------------------------------------
__global__ void zero_deg_kernel(int n) {
    int i = blockIdx.x * blockDim.x + threadIdx.x;
    if (i < n) g_deg[i] = 0;
}
__global__ void hist_kernel(const int* __restrict__ dst, int E) {
    int i = blockIdx.x * blockDim.x + threadIdx.x;
    if (i < E) atomicAdd(&g_deg[dst[i]], 1);
}
__global__ void scan_kernel(int n) {
    __shared__ int sums[1024];
    const int t = threadIdx.x;
    const int chunk = (n + 1023) >> 10;
    const int begin = t * chunk;
    const int end = min(begin + chunk, n);
    int s = 0;
    for (int i = begin; i < end; i++) s += g_deg[i];
    sums[t] = s;
    __syncthreads();
    for (int d = 1; d < 1024; d <<= 1) {
        int v = (t >= d) ? sums[t - d] : 0;
        __syncthreads();
        sums[t] += v;
        __syncthreads();
    }
    int run = (t == 0) ? 0 : sums[t - 1];
    if (t == 0) g_offs[0] = 0;
    for (int i = begin; i < end; i++) {
        g_cursor[i] = run;
        run += g_deg[i];
        g_offs[i + 1] = run;
    }
}
__global__ void scatter_kernel(const int* __restrict__ src, const int* __restrict__ dst,
                               const float* __restrict__ w, int E) {
    int i = blockIdx.x * blockDim.x + threadIdx.x;
    if (i < E) {
        int d = dst[i];
        int pos = atomicAdd(&g_cursor[d], 1);
        g_csr_src[pos] = src[i];
        g_csr_w[pos] = w[i];
    }
}

// ---------------------------------------------------------------------------
// prep: weights transposed single f16; x single f16
// ---------------------------------------------------------------------------
__global__ void cvt_w_kernel(const float* __restrict__ W0, const float* __restrict__ W1,
                             const float* __restrict__ Wmid, const float* __restrict__ W15) {
    int i = blockIdx.x * blockDim.x + threadIdx.x;
    if (i >= WT_TOTAL) return;
    float v;
    if (i < 32768) {
        int n = i >> 8, k = i & 255;
        v = W0[k * 128 + n];
    } else if (i < 65536) {
        int j = i - 32768;
        int n = j >> 8, k = j & 255;
        v = W1[k * 128 + n];
    } else if (i < 278528) {
        int j = i - 65536;
        int l = j >> 14, jj = j & 16383;
        int n = jj >> 7, k = jj & 127;
        v = Wmid[l * 16384 + k * 128 + n];
    } else {
        int j = i - 278528;
        int n = j / 1792, k = j % 1792;
        v = (n < 40) ? W15[(size_t)k * 40 + n] : 0.f;
    }
    g_wfh[i] = __float2half_rn(v);
}
__global__ void cvt_x_kernel(const float* __restrict__ x, int total) {
    int i = blockIdx.x * blockDim.x + threadIdx.x;
    if (i < total) g_xf16[i] = __float2half_rn(x[i]);
}

// ---------------------------------------------------------------------------
// fp16 GEMM: C[M,128] = A16[M,K] @ B16t[128,K]^T.
// ZMODE 0: fp32 out = acc + bias.  ZMODE 1: f16 out = acc * oscale.
// 2-stage cp.async pipeline, 8 warps, warp tile 32x64.
// ---------------------------------------------------------------------------
#define TILE_E (128 * LDK)
#define SMEMSZ_GF (2 * 2 * TILE_E * 2)

template<int ZMODE>
__global__ void __launch_bounds__(256) tgemmf_kernel(
    const __half* __restrict__ A16, const __half* __restrict__ B16,
    const float* __restrict__ bias, void* __restrict__ Cout,
    float oscale, int M, int K)
{
    extern __shared__ __half sh[];
    const int tid = threadIdx.x, lane = tid & 31, wid = tid >> 5;
    const int row0 = blockIdx.x * 128;
    const int wm = wid & 3, wn = wid >> 2;

    float acc[2][8][4];
#pragma unroll
    for (int a = 0; a < 2; a++)
#pragma unroll
        for (int b = 0; b < 8; b++)
#pragma unroll
            for (int c = 0; c < 4; c++) acc[a][b][c] = 0.f;

    const int a_r = (lane & 7) + ((lane >> 3) & 1) * 8;
    const int a_c = (lane >> 4) * 8;
    const int b_r = (lane & 7) + (lane >> 4) * 8;
    const int b_c = ((lane >> 3) & 1) * 8;
    const int nc = K >> 5;

    auto load_stage = [&](int st, int k0) {
        __half* sA = sh + st * 2 * TILE_E;
        __half* sB = sA + TILE_E;
#pragma unroll
        for (int i = tid; i < 512; i += 256) {
            int r = i >> 2, g = i & 3;
            uint32_t sz = (row0 + r < M) ? 16u : 0u;
            size_t go = (size_t)(row0 + r) * K + k0 + g * 8;
            cp16(s2u(sA + r * LDK + g * 8), A16 + go, sz);
        }
#pragma unroll
        for (int i = tid; i < 512; i += 256) {
            int r = i >> 2, g = i & 3;
            size_t go = (size_t)r * K + k0 + g * 8;
            cp16(s2u(sB + r * LDK + g * 8), B16 + go, 16u);
        }
        CP_COMMIT();
    };

    load_stage(0, 0);
    for (int c = 0; c < nc; c++) {
        if (c + 1 < nc) {
            load_stage((c + 1) & 1, (c + 1) << 5);
            asm volatile("cp.async.wait_group 1;");
        } else {
            asm volatile("cp.async.wait_group 0;");
        }
        __syncthreads();

        const int st = c & 1;
        const __half* sA = sh + st * 2 * TILE_E;
        const __half* sB = sA + TILE_E;
#pragma unroll
        for (int k16 = 0; k16 < 32; k16 += 16) {
            uint32_t a[2][4];
#pragma unroll
            for (int mt = 0; mt < 2; mt++) {
                int er = wm * 32 + mt * 16 + a_r;
                int ec = k16 + a_c;
                ldsm4(a[mt], s2u(sA + er * LDK + ec));
            }
#pragma unroll
            for (int p = 0; p < 4; p++) {
                int er = wn * 64 + p * 16 + b_r;
                int ec = k16 + b_c;
                uint32_t b[4];
                ldsm4(b, s2u(sB + er * LDK + ec));
#pragma unroll
                for (int mt = 0; mt < 2; mt++) {
                    mma_fp16(acc[mt][2 * p],     a[mt], b[0], b[1]);
                    mma_fp16(acc[mt][2 * p + 1], a[mt], b[2], b[3]);
                }
            }
        }
        __syncthreads();
    }

    const int er0 = row0 + wm * 32 + (lane >> 2);
    const int ec0 = wn * 64 + (lane & 3) * 2;
#pragma unroll
    for (int mt = 0; mt < 2; mt++) {
#pragma unroll
        for (int nt = 0; nt < 8; nt++) {
            int col = ec0 + nt * 8;
            float bx = 0.f, by = 0.f;
            if (ZMODE == 0) { bx = bias[col]; by = bias[col + 1]; }
            int r1 = er0 + mt * 16, r2 = r1 + 8;
#pragma unroll
            for (int half = 0; half < 2; half++) {
                int r = half ? r2 : r1;
                if (r >= M) continue;
                float vx = acc[mt][nt][half * 2];
                float vy = acc[mt][nt][half * 2 + 1];
                if (ZMODE == 0) {
                    *(float2*)((float*)Cout + (size_t)r * 128 + col) =
                        make_float2(vx + bx, vy + by);
                } else {
                    ((__half2*)Cout)[((size_t)r * 128 + col) >> 1] =
                        __floats2half2_rn(vx * oscale, vy * oscale);
                }
            }
        }
    }
}

// ---------------------------------------------------------------------------
// SpMM d=128: warp per node, f16 sup gather (2^-10).
// o = relu(agg*2^10 + bias) + residual; write slab (2^-15).
// RES16=0: residual from fp32 z.  RES16=1: residual from f16 slab * 2^15.
// ---------------------------------------------------------------------------
template<int RES16>
__global__ void __launch_bounds__(256) spmm_relu_res_kernel(
    const __half* __restrict__ support, const float* __restrict__ bias,
    const float* __restrict__ zres, const __half* __restrict__ res16,
    __half* __restrict__ out16, int n)
{
    const int node = (blockIdx.x * blockDim.x + threadIdx.x) >> 5;
    if (node >= n) return;
    const int lane = threadIdx.x & 31;
    const int s = g_offs[node], e = g_offs[node + 1];
    const uint2* sup2 = (const uint2*)support;

    float4 acc = make_float4(0.f, 0.f, 0.f, 0.f);
    int i = s;
    for (; i + 1 < e; i += 2) {
        int s0 = g_csr_src[i], s1 = g_csr_src[i + 1];
        float w0 = g_csr_w[i],  w1 = g_csr_w[i + 1];
        uint2 u0 = sup2[(size_t)s0 * 32 + lane];
        uint2 u1 = sup2[(size_t)s1 * 32 + lane];
        float2 a0 = __half22float2(*(const __half2*)&u0.x);
        float2 a1 = __half22float2(*(const __half2*)&u0.y);
        acc.x = fmaf(w0, a0.x, acc.x); acc.y = fmaf(w0, a0.y, acc.y);
        acc.z = fmaf(w0, a1.x, acc.z); acc.w = fmaf(w0, a1.y, acc.w);
        float2 b0 = __half22float2(*(const __half2*)&u1.x);
        float2 b1 = __half22float2(*(const __half2*)&u1.y);
        acc.x = fmaf(w1, b0.x, acc.x); acc.y = fmaf(w1, b0.y, acc.y);
        acc.z = fmaf(w1, b1.x, acc.z); acc.w = fmaf(w1, b1.y, acc.w);
    }
    if (i < e) {
        int s0 = g_csr_src[i];
        float w0 = g_csr_w[i];
        uint2 u0 = sup2[(size_t)s0 * 32 + lane];
        float2 a0 = __half22float2(*(const __half2*)&u0.x);
        float2 a1 = __half22float2(*(const __half2*)&u0.y);
        acc.x = fmaf(w0, a0.x, acc.x); acc.y = fmaf(w0, a0.y, acc.y);
        acc.z = fmaf(w0, a1.x, acc.z); acc.w = fmaf(w0, a1.y, acc.w);
    }
    acc.x *= SUP_UNSCALE; acc.y *= SUP_UNSCALE;
    acc.z *= SUP_UNSCALE; acc.w *= SUP_UNSCALE;

    float4 b = ((const float4*)bias)[lane];
    float4 r;
    if (RES16) {
        uint2 u = ((const uint2*)(res16 + (size_t)node * 128))[lane];
        float2 r0 = __half22float2(*(const __half2*)&u.x);
        float2 r1 = __half22float2(*(const __half2*)&u.y);
        r = make_float4(r0.x * SLAB_UNSCALE, r0.y * SLAB_UNSCALE,
                        r1.x * SLAB_UNSCALE, r1.y * SLAB_UNSCALE);
    } else {
        r = ((const float4*)zres)[(size_t)node * 32 + lane];
    }
    float4 o;
    o.x = fmaxf(acc.x + b.x, 0.f) + r.x;
    o.y = fmaxf(acc.y + b.y, 0.f) + r.y;
    o.z = fmaxf(acc.z + b.z, 0.f) + r.z;
    o.w = fmaxf(acc.w + b.w, 0.f) + r.w;

    uint2 w16;
    __half2 f0 = __floats2half2_rn(o.x * SLAB_SCALE, o.y * SLAB_SCALE);
    __half2 f1 = __floats2half2_rn(o.z * SLAB_SCALE, o.w * SLAB_SCALE);
    w16.x = *(uint32_t*)&f0;
    w16.y = *(uint32_t*)&f1;
    ((uint2*)(out16 + (size_t)node * 128))[lane] = w16;
}

// ---------------------------------------------------------------------------
// Final GEMM (fp16): C[M,40] = X_cat(f16, 2^-15)[M,1792] @ W15f[48,1792]^T * 2^15
// ---------------------------------------------------------------------------
#define BTILE_E (48 * LDK)
#define SMEMSZ_G40F (2 * (TILE_E + BTILE_E) * 2)

__global__ void __launch_bounds__(256) tgemm40f_kernel(
    const __half* __restrict__ H16, const __half* __restrict__ B16,
    float* __restrict__ C, int M)
{
    extern __shared__ __half sh[];
    const int tid = threadIdx.x, lane = tid & 31, wid = tid >> 5;
    const int row0 = blockIdx.x * 128;
    const size_t slabE = (size_t)M * 128;
    const int STG = TILE_E + BTILE_E;

    float acc[6][4];
#pragma unroll
    for (int a = 0; a < 6; a++)
#pragma unroll
        for (int c = 0; c < 4; c++) acc[a][c] = 0.f;

    const int a_r = (lane & 7) + ((lane >> 3) & 1) * 8;
    const int a_c = (lane >> 4) * 8;
    const int b_r = (lane & 7) + (lane >> 4) * 8;
    const int b_c = ((lane >> 3) & 1) * 8;

    auto load_stage = [&](int st, int c) {
        const int k0g = c * 32;
        const int slab = 13 - (k0g >> 7);
        const int kin = k0g & 127;
        const __half* A = H16 + (size_t)slab * slabE;
        __half* sA = sh + st * STG;
        __half* sB = sA + TILE_E;
#pragma unroll
        for (int i = tid; i < 512; i += 256) {
            int r = i >> 2, g = i & 3;
            uint32_t sz = (row0 + r < M) ? 16u : 0u;
            size_t go = (size_t)(row0 + r) * 128 + kin + g * 8;
            cp16(s2u(sA + r * LDK + g * 8), A + go, sz);
        }
        if (tid < 192) {
            int r = tid >> 2, g = tid & 3;
            size_t go = (size_t)r * 1792 + k0g + g * 8;
            cp16(s2u(sB + r * LDK + g * 8), B16 + go, 16u);
        }
        CP_COMMIT();
    };

    load_stage(0, 0);
    for (int c = 0; c < 56; c++) {
        if (c + 1 < 56) {
            load_stage((c + 1) & 1, c + 1);
            asm volatile("cp.async.wait_group 1;");
        } else {
            asm volatile("cp.async.wait_group 0;");
        }
        __syncthreads();

        const int st = c & 1;
        const __half* sA = sh + st * STG;
        const __half* sB = sA + TILE_E;
#pragma unroll
        for (int k16 = 0; k16 < 32; k16 += 16) {
            uint32_t a[4];
            int er = wid * 16 + a_r;
            int ec = k16 + a_c;
            ldsm4(a, s2u(sA + er * LDK + ec));
#pragma unroll
            for (int p = 0; p < 3; p++) {
                int br = p * 16 + b_r;
                int bc = k16 + b_c;
                uint32_t b[4];
                ldsm4(b, s2u(sB + br * LDK + bc));
                mma_fp16(acc[2 * p],     a, b[0], b[1]);
                mma_fp16(acc[2 * p + 1], a, b[2], b[3]);
            }
        }
        __syncthreads();
    }
    const int r1 = row0 + wid * 16 + (lane >> 2);
    const int r2 = r1 + 8;
#pragma unroll
    for (int nt = 0; nt < 5; nt++) {
        int col = nt * 8 + (lane & 3) * 2;
        if (r1 < M) *(float2*)(C + (size_t)r1 * 40 + col) =
            make_float2(acc[nt][0] * SLAB_UNSCALE, acc[nt][1] * SLAB_UNSCALE);
        if (r2 < M) *(float2*)(C + (size_t)r2 * 40 + col) =
            make_float2(acc[nt][2] * SLAB_UNSCALE, acc[nt][3] * SLAB_UNSCALE);
    }
}

// ---------------------------------------------------------------------------
// Final: agg40 + b15 + log_softmax. Warp per node. fp32 gather.
// ---------------------------------------------------------------------------
__global__ void __launch_bounds__(256) spmm40_lsm_kernel(
    const float* __restrict__ accum, const float* __restrict__ b15,
    float* __restrict__ out, int n)
{
    const int node = (blockIdx.x * blockDim.x + threadIdx.x) >> 5;
    if (node >= n) return;
    const int lane = threadIdx.x & 31;
    const int s = g_offs[node], e = g_offs[node + 1];

    float a1 = 0.f, a2 = 0.f;
    for (int i = s; i < e; i++) {
        int src = g_csr_src[i];
        float w = g_csr_w[i];
        const float* row = accum + (size_t)src * 40;
        a1 = fmaf(w, row[lane], a1);
        if (lane < 8) a2 = fmaf(w, row[32 + lane], a2);
    }
    float v1 = a1 + b15[lane];
    float v2 = (lane < 8) ? (a2 + b15[32 + lane]) : -3.0e38f;

    float m = fmaxf(v1, v2);
#pragma unroll
    for (int o = 16; o > 0; o >>= 1) m = fmaxf(m, __shfl_xor_sync(0xffffffffu, m, o));
    float sum = expf(v1 - m) + ((lane < 8) ? expf(v2 - m) : 0.f);
#pragma unroll
    for (int o = 16; o > 0; o >>= 1) sum += __shfl_xor_sync(0xffffffffu, sum, o);
    float ls = m + logf(sum);

    out[(size_t)node * 40 + lane] = v1 - ls;
    if (lane < 8) out[(size_t)node * 40 + 32 + lane] = v2 - ls;
}

// ---------------------------------------------------------------------------
// Launch
// ---------------------------------------------------------------------------
extern "C" void kernel_launch(void* const* d_in, const int* in_sizes, int n_in,
                              void* d_out, int out_size)
{
    const float* x    = (const float*)d_in[0];
    const int*   esrc = (const int*)  d_in[1];
    const int*   edst = (const int*)  d_in[2];
    const float* ew   = (const float*)d_in[3];
    const float* W0   = (const float*)d_in[4];
    const float* b0   = (const float*)d_in[5];
    const float* W1   = (const float*)d_in[6];
    const float* b1   = (const float*)d_in[7];
    const float* Wmid = (const float*)d_in[8];
    const float* bmid = (const float*)d_in[9];
    const float* W15  = (const float*)d_in[10];
    const float* b15  = (const float*)d_in[11];

    const int E = in_sizes[1];
    const int n = in_sizes[0] / 256;
    float* out = (float*)d_out;

    float *z, *accum;
    __half *sup, *hf16, *wfh, *xf16;
    cudaGetSymbolAddress((void**)&z,     g_z);
    cudaGetSymbolAddress((void**)&sup,   g_sup);
    cudaGetSymbolAddress((void**)&accum, g_acc);
    cudaGetSymbolAddress((void**)&wfh,   g_wfh);
    cudaGetSymbolAddress((void**)&xf16,  g_xf16);
    cudaGetSymbolAddress((void**)&hf16,  g_hf16);

    cudaFuncSetAttribute(tgemmf_kernel<0>, cudaFuncAttributeMaxDynamicSharedMemorySize, SMEMSZ_GF);
    cudaFuncSetAttribute(tgemmf_kernel<1>, cudaFuncAttributeMaxDynamicSharedMemorySize, SMEMSZ_GF);
    cudaFuncSetAttribute(tgemm40f_kernel,  cudaFuncAttributeMaxDynamicSharedMemorySize, SMEMSZ_G40F);

    const int TB = 256;
    const int gridE = (E + TB - 1) / TB;
    const int gridN = (n + TB - 1) / TB;
    const int gridT = (n + 127) / 128;
    const int gridSpmm = (n + 7) / 8;
    const size_t slab = (size_t)n * 128;

    // 1. CSR build + conversions
    zero_deg_kernel<<<gridN, TB>>>(n);
    hist_kernel<<<gridE, TB>>>(edst, E);
    scan_kernel<<<1, 1024>>>(n);
    scatter_kernel<<<gridE, TB>>>(esrc, edst, ew, E);
    cvt_w_kernel<<<(WT_TOTAL + TB - 1) / TB, TB>>>(W0, W1, Wmid, W15);
    cvt_x_kernel<<<(n * 256 + TB - 1) / TB, TB>>>(x, n * 256);

    // 2. layer 1: z = x@W0+b0 (fp32) ; sup = x@W1 (f16 2^-10) ; slab0
    tgemmf_kernel<0><<<gridT, 256, SMEMSZ_GF>>>(xf16, wfh + WOFF_W0, b0, z, 0.f, n, 256);
    tgemmf_kernel<1><<<gridT, 256, SMEMSZ_GF>>>(xf16, wfh + WOFF_W1, nullptr, sup, SUP_SCALE, n, 256);
    spmm_relu_res_kernel<0><<<gridSpmm, 256>>>(sup, b1, z, nullptr, hf16, n);

    // 3. mid layers: sup = slab_l @ Wmid[l] ; slab_{l+1} = relu(agg+b)+slab_l
    for (int l = 0; l < 13; l++) {
        tgemmf_kernel<1><<<gridT, 256, SMEMSZ_GF>>>(hf16 + (size_t)l * slab,
                                                    wfh + WOFF_MID + (size_t)l * 16384,
                                                    nullptr, sup, ACC2SUP, n, 128);
        spmm_relu_res_kernel<1><<<gridSpmm, 256>>>(sup, bmid + (size_t)l * 128,
                                                   nullptr, hf16 + (size_t)l * slab,
                                                   hf16 + (size_t)(l + 1) * slab, n);
    }

    // 4. P = X_cat @ W15
    tgemm40f_kernel<<<gridT, 256, SMEMSZ_G40F>>>(hf16, wfh + WOFF_W15, accum, n);

    // 5. out = log_softmax(agg40(P) + b15)
    spmm40_lsm_kernel<<<gridSpmm, 256>>>(accum, b15, out, n);
}

// round 13
// speedup vs baseline: 2.6617x; 1.0646x over previous
#include <cuda_runtime.h>
#include <cuda_fp16.h>
#include <math.h>
#include <stdint.h>

// ---------------------------------------------------------------------------
// ResGCN15 (sm_103 -> HMMA fp16 mma.sync everywhere).
// R12 + half-warp-per-node aggregation (LDG.128 gathers, unroll 4).
// Activations: scaled f16 slabs (2^-15) carrying the residual.
// Weights single f16 (transposed). sup stream f16 (2^-10).
// ---------------------------------------------------------------------------

#define MAX_N 50000
#define MAX_E 800000
#define NHID 128
#define NCLASS 40
#define LDK 40          // smem row stride (32 elems + 8 pad)

#define SUP_SCALE    0.0009765625f      // 2^-10 (sup stream)
#define SUP_UNSCALE  1024.0f
#define SLAB_SCALE   0.000030517578125f // 2^-15 (activation slabs)
#define SLAB_UNSCALE 32768.0f
#define ACC2SUP      32.0f              // 2^15 * 2^-10

#define WOFF_W0   0
#define WOFF_W1   32768
#define WOFF_MID  65536
#define WOFF_W15  278528
#define WT_TOTAL  364544

__device__ __align__(16) int   g_deg[MAX_N];
__device__ __align__(16) int   g_offs[MAX_N + 1];
__device__ __align__(16) int   g_cursor[MAX_N];
__device__ __align__(16) int   g_csr_src[MAX_E];
__device__ __align__(16) float g_csr_w[MAX_E];
__device__ __align__(16) float g_z[(size_t)MAX_N * NHID];
__device__ __align__(16) __half g_sup[(size_t)MAX_N * NHID];
__device__ __align__(16) float g_acc[(size_t)MAX_N * NCLASS];
__device__ __align__(16) __half g_wfh[WT_TOTAL];
__device__ __align__(16) __half g_xf16[(size_t)MAX_N * 256];
__device__ __align__(16) __half g_hf16[(size_t)14 * MAX_N * NHID];  // 2^-15

// ---------------------------------------------------------------------------
// helpers
// ---------------------------------------------------------------------------
__device__ __forceinline__ uint32_t s2u(const void* p) {
    return (uint32_t)__cvta_generic_to_shared(p);
}
__device__ __forceinline__ void ldsm4(uint32_t* r, uint32_t addr) {
    asm volatile("ldmatrix.sync.aligned.m8n8.x4.shared.b16 {%0,%1,%2,%3}, [%4];"
                 : "=r"(r[0]), "=r"(r[1]), "=r"(r[2]), "=r"(r[3]) : "r"(addr));
}
__device__ __forceinline__ void mma_fp16(float* d, const uint32_t* a,
                                         uint32_t b0, uint32_t b1) {
    asm volatile(
        "mma.sync.aligned.m16n8k16.row.col.f32.f16.f16.f32 "
        "{%0,%1,%2,%3}, {%4,%5,%6,%7}, {%8,%9}, {%0,%1,%2,%3};"
        : "+f"(d[0]), "+f"(d[1]), "+f"(d[2]), "+f"(d[3])
        : "r"(a[0]), "r"(a[1]), "r"(a[2]), "r"(a[3]), "r"(b0), "r"(b1));
}
__device__ __forceinline__ void cp16(uint32_t saddr, const void* gptr, uint32_t sz) {
    asm volatile("cp.async.cg.shared.global [%0], [%1], 16, %2;"
                 :: "r"(saddr), "l"(gptr), "r"(sz));
}
#define CP_COMMIT() asm volatile("cp.async.commit_group;")

// ---------------------------------------------------------------------------
// CSR build
// ---------------------------------------------------------------------------
__global__ void zero_deg_kernel(int n) {
    int i = blockIdx.x * blockDim.x + threadIdx.x;
    if (i < n) g_deg[i] = 0;
}
__global__ void hist_kernel(const int* __restrict__ dst, int E) {
    int i = blockIdx.x * blockDim.x + threadIdx.x;
    if (i < E) atomicAdd(&g_deg[dst[i]], 1);
}
__global__ void scan_kernel(int n) {
    __shared__ int sums[1024];
    const int t = threadIdx.x;
    const int chunk = (n + 1023) >> 10;
    const int begin = t * chunk;
    const int end = min(begin + chunk, n);
    int s = 0;
    for (int i = begin; i < end; i++) s += g_deg[i];
    sums[t] = s;
    __syncthreads();
    for (int d = 1; d < 1024; d <<= 1) {
        int v = (t >= d) ? sums[t - d] : 0;
        __syncthreads();
        sums[t] += v;
        __syncthreads();
    }
    int run = (t == 0) ? 0 : sums[t - 1];
    if (t == 0) g_offs[0] = 0;
    for (int i = begin; i < end; i++) {
        g_cursor[i] = run;
        run += g_deg[i];
        g_offs[i + 1] = run;
    }
}
__global__ void scatter_kernel(const int* __restrict__ src, const int* __restrict__ dst,
                               const float* __restrict__ w, int E) {
    int i = blockIdx.x * blockDim.x + threadIdx.x;
    if (i < E) {
        int d = dst[i];
        int pos = atomicAdd(&g_cursor[d], 1);
        g_csr_src[pos] = src[i];
        g_csr_w[pos] = w[i];
    }
}

// ---------------------------------------------------------------------------
// prep: weights transposed single f16; x single f16 (vectorized)
// ---------------------------------------------------------------------------
__global__ void cvt_w_kernel(const float* __restrict__ W0, const float* __restrict__ W1,
                             const float* __restrict__ Wmid, const float* __restrict__ W15) {
    int i = blockIdx.x * blockDim.x + threadIdx.x;
    if (i >= WT_TOTAL) return;
    float v;
    if (i < 32768) {
        int n = i >> 8, k = i & 255;
        v = W0[k * 128 + n];
    } else if (i < 65536) {
        int j = i - 32768;
        int n = j >> 8, k = j & 255;
        v = W1[k * 128 + n];
    } else if (i < 278528) {
        int j = i - 65536;
        int l = j >> 14, jj = j & 16383;
        int n = jj >> 7, k = jj & 127;
        v = Wmid[l * 16384 + k * 128 + n];
    } else {
        int j = i - 278528;
        int n = j / 1792, k = j % 1792;
        v = (n < 40) ? W15[(size_t)k * 40 + n] : 0.f;
    }
    g_wfh[i] = __float2half_rn(v);
}
__global__ void cvt_x_kernel(const float* __restrict__ x, int total2) {
    int i = blockIdx.x * blockDim.x + threadIdx.x;
    if (i < total2) {
        float2 v = ((const float2*)x)[i];
        ((__half2*)g_xf16)[i] = __floats2half2_rn(v.x, v.y);
    }
}

// ---------------------------------------------------------------------------
// fp16 GEMM: C[M,128] = A16[M,K] @ B16t[128,K]^T.
// ZMODE 0: fp32 out = acc + bias.  ZMODE 1: f16 out = acc * oscale.
// ---------------------------------------------------------------------------
#define TILE_E (128 * LDK)
#define SMEMSZ_GF (2 * 2 * TILE_E * 2)

template<int ZMODE>
__global__ void __launch_bounds__(256) tgemmf_kernel(
    const __half* __restrict__ A16, const __half* __restrict__ B16,
    const float* __restrict__ bias, void* __restrict__ Cout,
    float oscale, int M, int K)
{
    extern __shared__ __half sh[];
    const int tid = threadIdx.x, lane = tid & 31, wid = tid >> 5;
    const int row0 = blockIdx.x * 128;
    const int wm = wid & 3, wn = wid >> 2;

    float acc[2][8][4];
#pragma unroll
    for (int a = 0; a < 2; a++)
#pragma unroll
        for (int b = 0; b < 8; b++)
#pragma unroll
            for (int c = 0; c < 4; c++) acc[a][b][c] = 0.f;

    const int a_r = (lane & 7) + ((lane >> 3) & 1) * 8;
    const int a_c = (lane >> 4) * 8;
    const int b_r = (lane & 7) + (lane >> 4) * 8;
    const int b_c = ((lane >> 3) & 1) * 8;
    const int nc = K >> 5;

    auto load_stage = [&](int st, int k0) {
        __half* sA = sh + st * 2 * TILE_E;
        __half* sB = sA + TILE_E;
#pragma unroll
        for (int i = tid; i < 512; i += 256) {
            int r = i >> 2, g = i & 3;
            uint32_t sz = (row0 + r < M) ? 16u : 0u;
            size_t go = (size_t)(row0 + r) * K + k0 + g * 8;
            cp16(s2u(sA + r * LDK + g * 8), A16 + go, sz);
        }
#pragma unroll
        for (int i = tid; i < 512; i += 256) {
            int r = i >> 2, g = i & 3;
            size_t go = (size_t)r * K + k0 + g * 8;
            cp16(s2u(sB + r * LDK + g * 8), B16 + go, 16u);
        }
        CP_COMMIT();
    };

    load_stage(0, 0);
    for (int c = 0; c < nc; c++) {
        if (c + 1 < nc) {
            load_stage((c + 1) & 1, (c + 1) << 5);
            asm volatile("cp.async.wait_group 1;");
        } else {
            asm volatile("cp.async.wait_group 0;");
        }
        __syncthreads();

        const int st = c & 1;
        const __half* sA = sh + st * 2 * TILE_E;
        const __half* sB = sA + TILE_E;
#pragma unroll
        for (int k16 = 0; k16 < 32; k16 += 16) {
            uint32_t a[2][4];
#pragma unroll
            for (int mt = 0; mt < 2; mt++) {
                int er = wm * 32 + mt * 16 + a_r;
                int ec = k16 + a_c;
                ldsm4(a[mt], s2u(sA + er * LDK + ec));
            }
#pragma unroll
            for (int p = 0; p < 4; p++) {
                int er = wn * 64 + p * 16 + b_r;
                int ec = k16 + b_c;
                uint32_t b[4];
                ldsm4(b, s2u(sB + er * LDK + ec));
#pragma unroll
                for (int mt = 0; mt < 2; mt++) {
                    mma_fp16(acc[mt][2 * p],     a[mt], b[0], b[1]);
                    mma_fp16(acc[mt][2 * p + 1], a[mt], b[2], b[3]);
                }
            }
        }
        __syncthreads();
    }

    const int er0 = row0 + wm * 32 + (lane >> 2);
    const int ec0 = wn * 64 + (lane & 3) * 2;
#pragma unroll
    for (int mt = 0; mt < 2; mt++) {
#pragma unroll
        for (int nt = 0; nt < 8; nt++) {
            int col = ec0 + nt * 8;
            float bx = 0.f, by = 0.f;
            if (ZMODE == 0) { bx = bias[col]; by = bias[col + 1]; }
            int r1 = er0 + mt * 16, r2 = r1 + 8;
#pragma unroll
            for (int half = 0; half < 2; half++) {
                int r = half ? r2 : r1;
                if (r >= M) continue;
                float vx = acc[mt][nt][half * 2];
                float vy = acc[mt][nt][half * 2 + 1];
                if (ZMODE == 0) {
                    *(float2*)((float*)Cout + (size_t)r * 128 + col) =
                        make_float2(vx + bx, vy + by);
                } else {
                    ((__half2*)Cout)[((size_t)r * 128 + col) >> 1] =
                        __floats2half2_rn(vx * oscale, vy * oscale);
                }
            }
        }
    }
}

// ---------------------------------------------------------------------------
// SpMM d=128: HALF-WARP per node (16 lanes x 16B), unroll 4.
// o = relu(agg*2^10 + bias) + residual; write slab (2^-15).
// RES16=0: residual from fp32 z.  RES16=1: residual from f16 slab * 2^15.
// ---------------------------------------------------------------------------
template<int RES16>
__global__ void __launch_bounds__(256) spmm_relu_res_kernel(
    const __half* __restrict__ support, const float* __restrict__ bias,
    const float* __restrict__ zres, const __half* __restrict__ res16,
    __half* __restrict__ out16, int n)
{
    const int node = (blockIdx.x * blockDim.x + threadIdx.x) >> 4;
    if (node >= n) return;
    const int lane = threadIdx.x & 15;           // 16 lanes x 8 halves
    const int s = g_offs[node], e = g_offs[node + 1];
    const uint4* sup4 = (const uint4*)support;   // 16 uint4 per row

    float a[8];
#pragma unroll
    for (int j = 0; j < 8; j++) a[j] = 0.f;

    int i = s;
    for (; i + 3 < e; i += 4) {
        int si[4]; float wv[4]; uint4 u[4];
#pragma unroll
        for (int q = 0; q < 4; q++) { si[q] = g_csr_src[i + q]; wv[q] = g_csr_w[i + q]; }
#pragma unroll
        for (int q = 0; q < 4; q++) u[q] = sup4[(size_t)si[q] * 16 + lane];
#pragma unroll
        for (int q = 0; q < 4; q++) {
            float2 p0 = __half22float2(*(const __half2*)&u[q].x);
            float2 p1 = __half22float2(*(const __half2*)&u[q].y);
            float2 p2 = __half22float2(*(const __half2*)&u[q].z);
            float2 p3 = __half22float2(*(const __half2*)&u[q].w);
            a[0] = fmaf(wv[q], p0.x, a[0]); a[1] = fmaf(wv[q], p0.y, a[1]);
            a[2] = fmaf(wv[q], p1.x, a[2]); a[3] = fmaf(wv[q], p1.y, a[3]);
            a[4] = fmaf(wv[q], p2.x, a[4]); a[5] = fmaf(wv[q], p2.y, a[5]);
            a[6] = fmaf(wv[q], p3.x, a[6]); a[7] = fmaf(wv[q], p3.y, a[7]);
        }
    }
    for (; i < e; i++) {
        int s0 = g_csr_src[i];
        float w0 = g_csr_w[i];
        uint4 u = sup4[(size_t)s0 * 16 + lane];
        float2 p0 = __half22float2(*(const __half2*)&u.x);
        float2 p1 = __half22float2(*(const __half2*)&u.y);
        float2 p2 = __half22float2(*(const __half2*)&u.z);
        float2 p3 = __half22float2(*(const __half2*)&u.w);
        a[0] = fmaf(w0, p0.x, a[0]); a[1] = fmaf(w0, p0.y, a[1]);
        a[2] = fmaf(w0, p1.x, a[2]); a[3] = fmaf(w0, p1.y, a[3]);
        a[4] = fmaf(w0, p2.x, a[4]); a[5] = fmaf(w0, p2.y, a[5]);
        a[6] = fmaf(w0, p3.x, a[6]); a[7] = fmaf(w0, p3.y, a[7]);
    }
#pragma unroll
    for (int j = 0; j < 8; j++) a[j] *= SUP_UNSCALE;

    float4 b0 = *(const float4*)(bias + lane * 8);
    float4 b1 = *(const float4*)(bias + lane * 8 + 4);
    float r[8];
    if (RES16) {
        uint4 u = ((const uint4*)(res16 + (size_t)node * 128))[lane];
        float2 p0 = __half22float2(*(const __half2*)&u.x);
        float2 p1 = __half22float2(*(const __half2*)&u.y);
        float2 p2 = __half22float2(*(const __half2*)&u.z);
        float2 p3 = __half22float2(*(const __half2*)&u.w);
        r[0] = p0.x * SLAB_UNSCALE; r[1] = p0.y * SLAB_UNSCALE;
        r[2] = p1.x * SLAB_UNSCALE; r[3] = p1.y * SLAB_UNSCALE;
        r[4] = p2.x * SLAB_UNSCALE; r[5] = p2.y * SLAB_UNSCALE;
        r[6] = p3.x * SLAB_UNSCALE; r[7] = p3.y * SLAB_UNSCALE;
    } else {
        float4 z0 = *(const float4*)(zres + (size_t)node * 128 + lane * 8);
        float4 z1 = *(const float4*)(zres + (size_t)node * 128 + lane * 8 + 4);
        r[0] = z0.x; r[1] = z0.y; r[2] = z0.z; r[3] = z0.w;
        r[4] = z1.x; r[5] = z1.y; r[6] = z1.z; r[7] = z1.w;
    }
    float o[8];
    o[0] = fmaxf(a[0] + b0.x, 0.f) + r[0];
    o[1] = fmaxf(a[1] + b0.y, 0.f) + r[1];
    o[2] = fmaxf(a[2] + b0.z, 0.f) + r[2];
    o[3] = fmaxf(a[3] + b0.w, 0.f) + r[3];
    o[4] = fmaxf(a[4] + b1.x, 0.f) + r[4];
    o[5] = fmaxf(a[5] + b1.y, 0.f) + r[5];
    o[6] = fmaxf(a[6] + b1.z, 0.f) + r[6];
    o[7] = fmaxf(a[7] + b1.w, 0.f) + r[7];

    uint4 w16;
    __half2 f0 = __floats2half2_rn(o[0] * SLAB_SCALE, o[1] * SLAB_SCALE);
    __half2 f1 = __floats2half2_rn(o[2] * SLAB_SCALE, o[3] * SLAB_SCALE);
    __half2 f2 = __floats2half2_rn(o[4] * SLAB_SCALE, o[5] * SLAB_SCALE);
    __half2 f3 = __floats2half2_rn(o[6] * SLAB_SCALE, o[7] * SLAB_SCALE);
    w16.x = *(uint32_t*)&f0;
    w16.y = *(uint32_t*)&f1;
    w16.z = *(uint32_t*)&f2;
    w16.w = *(uint32_t*)&f3;
    ((uint4*)(out16 + (size_t)node * 128))[lane] = w16;
}

// ---------------------------------------------------------------------------
// Final GEMM (fp16): C[M,40] = X_cat(f16, 2^-15)[M,1792] @ W15f[48,1792]^T * 2^15
// ---------------------------------------------------------------------------
#define BTILE_E (48 * LDK)
#define SMEMSZ_G40F (2 * (TILE_E + BTILE_E) * 2)

__global__ void __launch_bounds__(256) tgemm40f_kernel(
    const __half* __restrict__ H16, const __half* __restrict__ B16,
    float* __restrict__ C, int M)
{
    extern __shared__ __half sh[];
    const int tid = threadIdx.x, lane = tid & 31, wid = tid >> 5;
    const int row0 = blockIdx.x * 128;
    const size_t slabE = (size_t)M * 128;
    const int STG = TILE_E + BTILE_E;

    float acc[6][4];
#pragma unroll
    for (int a = 0; a < 6; a++)
#pragma unroll
        for (int c = 0; c < 4; c++) acc[a][c] = 0.f;

    const int a_r = (lane & 7) + ((lane >> 3) & 1) * 8;
    const int a_c = (lane >> 4) * 8;
    const int b_r = (lane & 7) + (lane >> 4) * 8;
    const int b_c = ((lane >> 3) & 1) * 8;

    auto load_stage = [&](int st, int c) {
        const int k0g = c * 32;
        const int slab = 13 - (k0g >> 7);
        const int kin = k0g & 127;
        const __half* A = H16 + (size_t)slab * slabE;
        __half* sA = sh + st * STG;
        __half* sB = sA + TILE_E;
#pragma unroll
        for (int i = tid; i < 512; i += 256) {
            int r = i >> 2, g = i & 3;
            uint32_t sz = (row0 + r < M) ? 16u : 0u;
            size_t go = (size_t)(row0 + r) * 128 + kin + g * 8;
            cp16(s2u(sA + r * LDK + g * 8), A + go, sz);
        }
        if (tid < 192) {
            int r = tid >> 2, g = tid & 3;
            size_t go = (size_t)r * 1792 + k0g + g * 8;
            cp16(s2u(sB + r * LDK + g * 8), B16 + go, 16u);
        }
        CP_COMMIT();
    };

    load_stage(0, 0);
    for (int c = 0; c < 56; c++) {
        if (c + 1 < 56) {
            load_stage((c + 1) & 1, c + 1);
            asm volatile("cp.async.wait_group 1;");
        } else {
            asm volatile("cp.async.wait_group 0;");
        }
        __syncthreads();

        const int st = c & 1;
        const __half* sA = sh + st * STG;
        const __half* sB = sA + TILE_E;
#pragma unroll
        for (int k16 = 0; k16 < 32; k16 += 16) {
            uint32_t a[4];
            int er = wid * 16 + a_r;
            int ec = k16 + a_c;
            ldsm4(a, s2u(sA + er * LDK + ec));
#pragma unroll
            for (int p = 0; p < 3; p++) {
                int br = p * 16 + b_r;
                int bc = k16 + b_c;
                uint32_t b[4];
                ldsm4(b, s2u(sB + br * LDK + bc));
                mma_fp16(acc[2 * p],     a, b[0], b[1]);
                mma_fp16(acc[2 * p + 1], a, b[2], b[3]);
            }
        }
        __syncthreads();
    }
    const int r1 = row0 + wid * 16 + (lane >> 2);
    const int r2 = r1 + 8;
#pragma unroll
    for (int nt = 0; nt < 5; nt++) {
        int col = nt * 8 + (lane & 3) * 2;
        if (r1 < M) *(float2*)(C + (size_t)r1 * 40 + col) =
            make_float2(acc[nt][0] * SLAB_UNSCALE, acc[nt][1] * SLAB_UNSCALE);
        if (r2 < M) *(float2*)(C + (size_t)r2 * 40 + col) =
            make_float2(acc[nt][2] * SLAB_UNSCALE, acc[nt][3] * SLAB_UNSCALE);
    }
}

// ---------------------------------------------------------------------------
// Final: agg40 + b15 + log_softmax. Warp per node. fp32 gather.
// ---------------------------------------------------------------------------
__global__ void __launch_bounds__(256) spmm40_lsm_kernel(
    const float* __restrict__ accum, const float* __restrict__ b15,
    float* __restrict__ out, int n)
{
    const int node = (blockIdx.x * blockDim.x + threadIdx.x) >> 5;
    if (node >= n) return;
    const int lane = threadIdx.x & 31;
    const int s = g_offs[node], e = g_offs[node + 1];

    float a1 = 0.f, a2 = 0.f;
    for (int i = s; i < e; i++) {
        int src = g_csr_src[i];
        float w = g_csr_w[i];
        const float* row = accum + (size_t)src * 40;
        a1 = fmaf(w, row[lane], a1);
        if (lane < 8) a2 = fmaf(w, row[32 + lane], a2);
    }
    float v1 = a1 + b15[lane];
    float v2 = (lane < 8) ? (a2 + b15[32 + lane]) : -3.0e38f;

    float m = fmaxf(v1, v2);
#pragma unroll
    for (int o = 16; o > 0; o >>= 1) m = fmaxf(m, __shfl_xor_sync(0xffffffffu, m, o));
    float sum = expf(v1 - m) + ((lane < 8) ? expf(v2 - m) : 0.f);
#pragma unroll
    for (int o = 16; o > 0; o >>= 1) sum += __shfl_xor_sync(0xffffffffu, sum, o);
    float ls = m + logf(sum);

    out[(size_t)node * 40 + lane] = v1 - ls;
    if (lane < 8) out[(size_t)node * 40 + 32 + lane] = v2 - ls;
}

// ---------------------------------------------------------------------------
// Launch
// ---------------------------------------------------------------------------
extern "C" void kernel_launch(void* const* d_in, const int* in_sizes, int n_in,
                              void* d_out, int out_size)
{
    const float* x    = (const float*)d_in[0];
    const int*   esrc = (const int*)  d_in[1];
    const int*   edst = (const int*)  d_in[2];
    const float* ew   = (const float*)d_in[3];
    const float* W0   = (const float*)d_in[4];
    const float* b0   = (const float*)d_in[5];
    const float* W1   = (const float*)d_in[6];
    const float* b1   = (const float*)d_in[7];
    const float* Wmid = (const float*)d_in[8];
    const float* bmid = (const float*)d_in[9];
    const float* W15  = (const float*)d_in[10];
    const float* b15  = (const float*)d_in[11];

    const int E = in_sizes[1];
    const int n = in_sizes[0] / 256;
    float* out = (float*)d_out;

    float *z, *accum;
    __half *sup, *hf16, *wfh, *xf16;
    cudaGetSymbolAddress((void**)&z,     g_z);
    cudaGetSymbolAddress((void**)&sup,   g_sup);
    cudaGetSymbolAddress((void**)&accum, g_acc);
    cudaGetSymbolAddress((void**)&wfh,   g_wfh);
    cudaGetSymbolAddress((void**)&xf16,  g_xf16);
    cudaGetSymbolAddress((void**)&hf16,  g_hf16);

    cudaFuncSetAttribute(tgemmf_kernel<0>, cudaFuncAttributeMaxDynamicSharedMemorySize, SMEMSZ_GF);
    cudaFuncSetAttribute(tgemmf_kernel<1>, cudaFuncAttributeMaxDynamicSharedMemorySize, SMEMSZ_GF);
    cudaFuncSetAttribute(tgemm40f_kernel,  cudaFuncAttributeMaxDynamicSharedMemorySize, SMEMSZ_G40F);

    const int TB = 256;
    const int gridE = (E + TB - 1) / TB;
    const int gridN = (n + TB - 1) / TB;
    const int gridT = (n + 127) / 128;
    const int gridSpmm16 = (n + 15) / 16;     // 16 nodes per 256-thread block
    const int gridSpmm32 = (n + 7) / 8;       // warp-per-node (lsm)
    const size_t slab = (size_t)n * 128;

    // 1. CSR build + conversions
    zero_deg_kernel<<<gridN, TB>>>(n);
    hist_kernel<<<gridE, TB>>>(edst, E);
    scan_kernel<<<1, 1024>>>(n);
    scatter_kernel<<<gridE, TB>>>(esrc, edst, ew, E);
    cvt_w_kernel<<<(WT_TOTAL + TB - 1) / TB, TB>>>(W0, W1, Wmid, W15);
    cvt_x_kernel<<<(n * 128 + TB - 1) / TB, TB>>>(x, n * 128);

    // 2. layer 1: z = x@W0+b0 (fp32) ; sup = x@W1 (f16 2^-10) ; slab0
    tgemmf_kernel<0><<<gridT, 256, SMEMSZ_GF>>>(xf16, wfh + WOFF_W0, b0, z, 0.f, n, 256);
    tgemmf_kernel<1><<<gridT, 256, SMEMSZ_GF>>>(xf16, wfh + WOFF_W1, nullptr, sup, SUP_SCALE, n, 256);
    spmm_relu_res_kernel<0><<<gridSpmm16, 256>>>(sup, b1, z, nullptr, hf16, n);

    // 3. mid layers: sup = slab_l @ Wmid[l] ; slab_{l+1} = relu(agg+b)+slab_l
    for (int l = 0; l < 13; l++) {
        tgemmf_kernel<1><<<gridT, 256, SMEMSZ_GF>>>(hf16 + (size_t)l * slab,
                                                    wfh + WOFF_MID + (size_t)l * 16384,
                                                    nullptr, sup, ACC2SUP, n, 128);
        spmm_relu_res_kernel<1><<<gridSpmm16, 256>>>(sup, bmid + (size_t)l * 128,
                                                     nullptr, hf16 + (size_t)l * slab,
                                                     hf16 + (size_t)(l + 1) * slab, n);
    }

    // 4. P = X_cat @ W15
    tgemm40f_kernel<<<gridT, 256, SMEMSZ_G40F>>>(hf16, wfh + WOFF_W15, accum, n);

    // 5. out = log_softmax(agg40(P) + b15)
    spmm40_lsm_kernel<<<gridSpmm32, 256>>>(accum, b15, out, n);
}

// round 14
// speedup vs baseline: 2.6753x; 1.0051x over previous
#include <cuda_runtime.h>
#include <cuda_fp16.h>
#include <math.h>
#include <stdint.h>

// ---------------------------------------------------------------------------
// ResGCN15 (sm_103 -> HMMA fp16 mma.sync everywhere).
// R13 + PDL (programmatic dependent launch) on the whole chain + packed CSR.
// Activations: scaled f16 slabs (2^-15) carrying the residual.
// Weights single f16 (transposed). sup stream f16 (2^-10).
// ---------------------------------------------------------------------------

#define MAX_N 50000
#define MAX_E 800000
#define NHID 128
#define NCLASS 40
#define LDK 40          // smem row stride (32 elems + 8 pad)

#define SUP_SCALE    0.0009765625f      // 2^-10 (sup stream)
#define SUP_UNSCALE  1024.0f
#define SLAB_SCALE   0.000030517578125f // 2^-15 (activation slabs)
#define SLAB_UNSCALE 32768.0f
#define ACC2SUP      32.0f              // 2^15 * 2^-10

#define WOFF_W0   0
#define WOFF_W1   32768
#define WOFF_MID  65536
#define WOFF_W15  278528
#define WT_TOTAL  364544

__device__ __align__(16) int   g_deg[MAX_N];
__device__ __align__(16) int   g_offs[MAX_N + 1];
__device__ __align__(16) int   g_cursor[MAX_N];
__device__ __align__(16) int2  g_csr[MAX_E];        // (src, weight bits)
__device__ __align__(16) float g_z[(size_t)MAX_N * NHID];
__device__ __align__(16) __half g_sup[(size_t)MAX_N * NHID];
__device__ __align__(16) float g_acc[(size_t)MAX_N * NCLASS];
__device__ __align__(16) __half g_wfh[WT_TOTAL];
__device__ __align__(16) __half g_xf16[(size_t)MAX_N * 256];
__device__ __align__(16) __half g_hf16[(size_t)14 * MAX_N * NHID];  // 2^-15

// ---------------------------------------------------------------------------
// helpers
// ---------------------------------------------------------------------------
__device__ __forceinline__ uint32_t s2u(const void* p) {
    return (uint32_t)__cvta_generic_to_shared(p);
}
__device__ __forceinline__ void ldsm4(uint32_t* r, uint32_t addr) {
    asm volatile("ldmatrix.sync.aligned.m8n8.x4.shared.b16 {%0,%1,%2,%3}, [%4];"
                 : "=r"(r[0]), "=r"(r[1]), "=r"(r[2]), "=r"(r[3]) : "r"(addr));
}
__device__ __forceinline__ void mma_fp16(float* d, const uint32_t* a,
                                         uint32_t b0, uint32_t b1) {
    asm volatile(
        "mma.sync.aligned.m16n8k16.row.col.f32.f16.f16.f32 "
        "{%0,%1,%2,%3}, {%4,%5,%6,%7}, {%8,%9}, {%0,%1,%2,%3};"
        : "+f"(d[0]), "+f"(d[1]), "+f"(d[2]), "+f"(d[3])
        : "r"(a[0]), "r"(a[1]), "r"(a[2]), "r"(a[3]), "r"(b0), "r"(b1));
}
__device__ __forceinline__ void cp16(uint32_t saddr, const void* gptr, uint32_t sz) {
    asm volatile("cp.async.cg.shared.global [%0], [%1], 16, %2;"
                 :: "r"(saddr), "l"(gptr), "r"(sz));
}
#define CP_COMMIT() asm volatile("cp.async.commit_group;")
#define GRID_SYNC() cudaGridDependencySynchronize()

// ---------------------------------------------------------------------------
// CSR build
// ---------------------------------------------------------------------------
__global__ void zero_deg_kernel(int n) {
    GRID_SYNC();
    int i = blockIdx.x * blockDim.x + threadIdx.x;
    if (i < n) g_deg[i] = 0;
}
__global__ void hist_kernel(const int* __restrict__ dst, int E) {
    GRID_SYNC();
    int i = blockIdx.x * blockDim.x + threadIdx.x;
    if (i < E) atomicAdd(&g_deg[dst[i]], 1);
}
__global__ void scan_kernel(int n) {
    __shared__ int sums[1024];
    GRID_SYNC();
    const int t = threadIdx.x;
    const int chunk = (n + 1023) >> 10;
    const int begin = t * chunk;
    const int end = min(begin + chunk, n);
    int s = 0;
    for (int i = begin; i < end; i++) s += g_deg[i];
    sums[t] = s;
    __syncthreads();
    for (int d = 1; d < 1024; d <<= 1) {
        int v = (t >= d) ? sums[t - d] : 0;
        __syncthreads();
        sums[t] += v;
        __syncthreads();
    }
    int run = (t == 0) ? 0 : sums[t - 1];
    if (t == 0) g_offs[0] = 0;
    for (int i = begin; i < end; i++) {
        g_cursor[i] = run;
        run += g_deg[i];
        g_offs[i + 1] = run;
    }
}
__global__ void scatter_kernel(const int* __restrict__ src, const int* __restrict__ dst,
                               const float* __restrict__ w, int E) {
    GRID_SYNC();
    int i = blockIdx.x * blockDim.x + threadIdx.x;
    if (i < E) {
        int d = dst[i];
        int pos = atomicAdd(&g_cursor[d], 1);
        g_csr[pos] = make_int2(src[i], __float_as_int(w[i]));
    }
}

// ---------------------------------------------------------------------------
// prep: weights transposed single f16; x single f16 (vectorized)
// ---------------------------------------------------------------------------
__global__ void cvt_w_kernel(const float* __restrict__ W0, const float* __restrict__ W1,
                             const float* __restrict__ Wmid, const float* __restrict__ W15) {
    GRID_SYNC();
    int i = blockIdx.x * blockDim.x + threadIdx.x;
    if (i >= WT_TOTAL) return;
    float v;
    if (i < 32768) {
        int n = i >> 8, k = i & 255;
        v = W0[k * 128 + n];
    } else if (i < 65536) {
        int j = i - 32768;
        int n = j >> 8, k = j & 255;
        v = W1[k * 128 + n];
    } else if (i < 278528) {
        int j = i - 65536;
        int l = j >> 14, jj = j & 16383;
        int n = jj >> 7, k = jj & 127;
        v = Wmid[l * 16384 + k * 128 + n];
    } else {
        int j = i - 278528;
        int n = j / 1792, k = j % 1792;
        v = (n < 40) ? W15[(size_t)k * 40 + n] : 0.f;
    }
    g_wfh[i] = __float2half_rn(v);
}
__global__ void cvt_x_kernel(const float* __restrict__ x, int total2) {
    GRID_SYNC();
    int i = blockIdx.x * blockDim.x + threadIdx.x;
    if (i < total2) {
        float2 v = ((const float2*)x)[i];
        ((__half2*)g_xf16)[i] = __floats2half2_rn(v.x, v.y);
    }
}

// ---------------------------------------------------------------------------
// fp16 GEMM: C[M,128] = A16[M,K] @ B16t[128,K]^T.
// ZMODE 0: fp32 out = acc + bias.  ZMODE 1: f16 out = acc * oscale.
// ---------------------------------------------------------------------------
#define TILE_E (128 * LDK)
#define SMEMSZ_GF (2 * 2 * TILE_E * 2)

template<int ZMODE>
__global__ void __launch_bounds__(256) tgemmf_kernel(
    const __half* __restrict__ A16, const __half* __restrict__ B16,
    const float* __restrict__ bias, void* __restrict__ Cout,
    float oscale, int M, int K)
{
    extern __shared__ __half sh[];
    const int tid = threadIdx.x, lane = tid & 31, wid = tid >> 5;
    const int row0 = blockIdx.x * 128;
    const int wm = wid & 3, wn = wid >> 2;

    float acc[2][8][4];
#pragma unroll
    for (int a = 0; a < 2; a++)
#pragma unroll
        for (int b = 0; b < 8; b++)
#pragma unroll
            for (int c = 0; c < 4; c++) acc[a][b][c] = 0.f;

    const int a_r = (lane & 7) + ((lane >> 3) & 1) * 8;
    const int a_c = (lane >> 4) * 8;
    const int b_r = (lane & 7) + (lane >> 4) * 8;
    const int b_c = ((lane >> 3) & 1) * 8;
    const int nc = K >> 5;

    auto load_stage = [&](int st, int k0) {
        __half* sA = sh + st * 2 * TILE_E;
        __half* sB = sA + TILE_E;
#pragma unroll
        for (int i = tid; i < 512; i += 256) {
            int r = i >> 2, g = i & 3;
            uint32_t sz = (row0 + r < M) ? 16u : 0u;
            size_t go = (size_t)(row0 + r) * K + k0 + g * 8;
            cp16(s2u(sA + r * LDK + g * 8), A16 + go, sz);
        }
#pragma unroll
        for (int i = tid; i < 512; i += 256) {
            int r = i >> 2, g = i & 3;
            size_t go = (size_t)r * K + k0 + g * 8;
            cp16(s2u(sB + r * LDK + g * 8), B16 + go, 16u);
        }
        CP_COMMIT();
    };

    GRID_SYNC();
    load_stage(0, 0);
    for (int c = 0; c < nc; c++) {
        if (c + 1 < nc) {
            load_stage((c + 1) & 1, (c + 1) << 5);
            asm volatile("cp.async.wait_group 1;");
        } else {
            asm volatile("cp.async.wait_group 0;");
        }
        __syncthreads();

        const int st = c & 1;
        const __half* sA = sh + st * 2 * TILE_E;
        const __half* sB = sA + TILE_E;
#pragma unroll
        for (int k16 = 0; k16 < 32; k16 += 16) {
            uint32_t a[2][4];
#pragma unroll
            for (int mt = 0; mt < 2; mt++) {
                int er = wm * 32 + mt * 16 + a_r;
                int ec = k16 + a_c;
                ldsm4(a[mt], s2u(sA + er * LDK + ec));
            }
#pragma unroll
            for (int p = 0; p < 4; p++) {
                int er = wn * 64 + p * 16 + b_r;
                int ec = k16 + b_c;
                uint32_t b[4];
                ldsm4(b, s2u(sB + er * LDK + ec));
#pragma unroll
                for (int mt = 0; mt < 2; mt++) {
                    mma_fp16(acc[mt][2 * p],     a[mt], b[0], b[1]);
                    mma_fp16(acc[mt][2 * p + 1], a[mt], b[2], b[3]);
                }
            }
        }
        __syncthreads();
    }

    const int er0 = row0 + wm * 32 + (lane >> 2);
    const int ec0 = wn * 64 + (lane & 3) * 2;
#pragma unroll
    for (int mt = 0; mt < 2; mt++) {
#pragma unroll
        for (int nt = 0; nt < 8; nt++) {
            int col = ec0 + nt * 8;
            float bx = 0.f, by = 0.f;
            if (ZMODE == 0) { bx = bias[col]; by = bias[col + 1]; }
            int r1 = er0 + mt * 16, r2 = r1 + 8;
#pragma unroll
            for (int half = 0; half < 2; half++) {
                int r = half ? r2 : r1;
                if (r >= M) continue;
                float vx = acc[mt][nt][half * 2];
                float vy = acc[mt][nt][half * 2 + 1];
                if (ZMODE == 0) {
                    *(float2*)((float*)Cout + (size_t)r * 128 + col) =
                        make_float2(vx + bx, vy + by);
                } else {
                    ((__half2*)Cout)[((size_t)r * 128 + col) >> 1] =
                        __floats2half2_rn(vx * oscale, vy * oscale);
                }
            }
        }
    }
}

// ---------------------------------------------------------------------------
// SpMM d=128: HALF-WARP per node (16 lanes x 16B), unroll 4, packed CSR.
// o = relu(agg*2^10 + bias) + residual; write slab (2^-15).
// RES16=0: residual from fp32 z.  RES16=1: residual from f16 slab * 2^15.
// ---------------------------------------------------------------------------
template<int RES16>
__global__ void __launch_bounds__(256) spmm_relu_res_kernel(
    const __half* __restrict__ support, const float* __restrict__ bias,
    const float* __restrict__ zres, const __half* __restrict__ res16,
    __half* __restrict__ out16, int n)
{
    GRID_SYNC();
    const int node = (blockIdx.x * blockDim.x + threadIdx.x) >> 4;
    if (node >= n) return;
    const int lane = threadIdx.x & 15;           // 16 lanes x 8 halves
    const int s = g_offs[node], e = g_offs[node + 1];
    const uint4* sup4 = (const uint4*)support;   // 16 uint4 per row

    float a[8];
#pragma unroll
    for (int j = 0; j < 8; j++) a[j] = 0.f;

    int i = s;
    for (; i + 3 < e; i += 4) {
        int2 ew[4]; uint4 u[4];
#pragma unroll
        for (int q = 0; q < 4; q++) ew[q] = g_csr[i + q];
#pragma unroll
        for (int q = 0; q < 4; q++) u[q] = sup4[(size_t)ew[q].x * 16 + lane];
#pragma unroll
        for (int q = 0; q < 4; q++) {
            float wv = __int_as_float(ew[q].y);
            float2 p0 = __half22float2(*(const __half2*)&u[q].x);
            float2 p1 = __half22float2(*(const __half2*)&u[q].y);
            float2 p2 = __half22float2(*(const __half2*)&u[q].z);
            float2 p3 = __half22float2(*(const __half2*)&u[q].w);
            a[0] = fmaf(wv, p0.x, a[0]); a[1] = fmaf(wv, p0.y, a[1]);
            a[2] = fmaf(wv, p1.x, a[2]); a[3] = fmaf(wv, p1.y, a[3]);
            a[4] = fmaf(wv, p2.x, a[4]); a[5] = fmaf(wv, p2.y, a[5]);
            a[6] = fmaf(wv, p3.x, a[6]); a[7] = fmaf(wv, p3.y, a[7]);
        }
    }
    for (; i < e; i++) {
        int2 ew = g_csr[i];
        float w0 = __int_as_float(ew.y);
        uint4 u = sup4[(size_t)ew.x * 16 + lane];
        float2 p0 = __half22float2(*(const __half2*)&u.x);
        float2 p1 = __half22float2(*(const __half2*)&u.y);
        float2 p2 = __half22float2(*(const __half2*)&u.z);
        float2 p3 = __half22float2(*(const __half2*)&u.w);
        a[0] = fmaf(w0, p0.x, a[0]); a[1] = fmaf(w0, p0.y, a[1]);
        a[2] = fmaf(w0, p1.x, a[2]); a[3] = fmaf(w0, p1.y, a[3]);
        a[4] = fmaf(w0, p2.x, a[4]); a[5] = fmaf(w0, p2.y, a[5]);
        a[6] = fmaf(w0, p3.x, a[6]); a[7] = fmaf(w0, p3.y, a[7]);
    }
#pragma unroll
    for (int j = 0; j < 8; j++) a[j] *= SUP_UNSCALE;

    float4 b0 = *(const float4*)(bias + lane * 8);
    float4 b1 = *(const float4*)(bias + lane * 8 + 4);
    float r[8];
    if (RES16) {
        uint4 u = ((const uint4*)(res16 + (size_t)node * 128))[lane];
        float2 p0 = __half22float2(*(const __half2*)&u.x);
        float2 p1 = __half22float2(*(const __half2*)&u.y);
        float2 p2 = __half22float2(*(const __half2*)&u.z);
        float2 p3 = __half22float2(*(const __half2*)&u.w);
        r[0] = p0.x * SLAB_UNSCALE; r[1] = p0.y * SLAB_UNSCALE;
        r[2] = p1.x * SLAB_UNSCALE; r[3] = p1.y * SLAB_UNSCALE;
        r[4] = p2.x * SLAB_UNSCALE; r[5] = p2.y * SLAB_UNSCALE;
        r[6] = p3.x * SLAB_UNSCALE; r[7] = p3.y * SLAB_UNSCALE;
    } else {
        float4 z0 = *(const float4*)(zres + (size_t)node * 128 + lane * 8);
        float4 z1 = *(const float4*)(zres + (size_t)node * 128 + lane * 8 + 4);
        r[0] = z0.x; r[1] = z0.y; r[2] = z0.z; r[3] = z0.w;
        r[4] = z1.x; r[5] = z1.y; r[6] = z1.z; r[7] = z1.w;
    }
    float o[8];
    o[0] = fmaxf(a[0] + b0.x, 0.f) + r[0];
    o[1] = fmaxf(a[1] + b0.y, 0.f) + r[1];
    o[2] = fmaxf(a[2] + b0.z, 0.f) + r[2];
    o[3] = fmaxf(a[3] + b0.w, 0.f) + r[3];
    o[4] = fmaxf(a[4] + b1.x, 0.f) + r[4];
    o[5] = fmaxf(a[5] + b1.y, 0.f) + r[5];
    o[6] = fmaxf(a[6] + b1.z, 0.f) + r[6];
    o[7] = fmaxf(a[7] + b1.w, 0.f) + r[7];

    uint4 w16;
    __half2 f0 = __floats2half2_rn(o[0] * SLAB_SCALE, o[1] * SLAB_SCALE);
    __half2 f1 = __floats2half2_rn(o[2] * SLAB_SCALE, o[3] * SLAB_SCALE);
    __half2 f2 = __floats2half2_rn(o[4] * SLAB_SCALE, o[5] * SLAB_SCALE);
    __half2 f3 = __floats2half2_rn(o[6] * SLAB_SCALE, o[7] * SLAB_SCALE);
    w16.x = *(uint32_t*)&f0;
    w16.y = *(uint32_t*)&f1;
    w16.z = *(uint32_t*)&f2;
    w16.w = *(uint32_t*)&f3;
    ((uint4*)(out16 + (size_t)node * 128))[lane] = w16;
}

// ---------------------------------------------------------------------------
// Final GEMM (fp16): C[M,40] = X_cat(f16, 2^-15)[M,1792] @ W15f[48,1792]^T * 2^15
// ---------------------------------------------------------------------------
#define BTILE_E (48 * LDK)
#define SMEMSZ_G40F (2 * (TILE_E + BTILE_E) * 2)

__global__ void __launch_bounds__(256) tgemm40f_kernel(
    const __half* __restrict__ H16, const __half* __restrict__ B16,
    float* __restrict__ C, int M)
{
    extern __shared__ __half sh[];
    const int tid = threadIdx.x, lane = tid & 31, wid = tid >> 5;
    const int row0 = blockIdx.x * 128;
    const size_t slabE = (size_t)M * 128;
    const int STG = TILE_E + BTILE_E;

    float acc[6][4];
#pragma unroll
    for (int a = 0; a < 6; a++)
#pragma unroll
        for (int c = 0; c < 4; c++) acc[a][c] = 0.f;

    const int a_r = (lane & 7) + ((lane >> 3) & 1) * 8;
    const int a_c = (lane >> 4) * 8;
    const int b_r = (lane & 7) + (lane >> 4) * 8;
    const int b_c = ((lane >> 3) & 1) * 8;

    auto load_stage = [&](int st, int c) {
        const int k0g = c * 32;
        const int slab = 13 - (k0g >> 7);
        const int kin = k0g & 127;
        const __half* A = H16 + (size_t)slab * slabE;
        __half* sA = sh + st * STG;
        __half* sB = sA + TILE_E;
#pragma unroll
        for (int i = tid; i < 512; i += 256) {
            int r = i >> 2, g = i & 3;
            uint32_t sz = (row0 + r < M) ? 16u : 0u;
            size_t go = (size_t)(row0 + r) * 128 + kin + g * 8;
            cp16(s2u(sA + r * LDK + g * 8), A + go, sz);
        }
        if (tid < 192) {
            int r = tid >> 2, g = tid & 3;
            size_t go = (size_t)r * 1792 + k0g + g * 8;
            cp16(s2u(sB + r * LDK + g * 8), B16 + go, 16u);
        }
        CP_COMMIT();
    };

    GRID_SYNC();
    load_stage(0, 0);
    for (int c = 0; c < 56; c++) {
        if (c + 1 < 56) {
            load_stage((c + 1) & 1, c + 1);
            asm volatile("cp.async.wait_group 1;");
        } else {
            asm volatile("cp.async.wait_group 0;");
        }
        __syncthreads();

        const int st = c & 1;
        const __half* sA = sh + st * STG;
        const __half* sB = sA + TILE_E;
#pragma unroll
        for (int k16 = 0; k16 < 32; k16 += 16) {
            uint32_t a[4];
            int er = wid * 16 + a_r;
            int ec = k16 + a_c;
            ldsm4(a, s2u(sA + er * LDK + ec));
#pragma unroll
            for (int p = 0; p < 3; p++) {
                int br = p * 16 + b_r;
                int bc = k16 + b_c;
                uint32_t b[4];
                ldsm4(b, s2u(sB + br * LDK + bc));
                mma_fp16(acc[2 * p],     a, b[0], b[1]);
                mma_fp16(acc[2 * p + 1], a, b[2], b[3]);
            }
        }
        __syncthreads();
    }
    const int r1 = row0 + wid * 16 + (lane >> 2);
    const int r2 = r1 + 8;
#pragma unroll
    for (int nt = 0; nt < 5; nt++) {
        int col = nt * 8 + (lane & 3) * 2;
        if (r1 < M) *(float2*)(C + (size_t)r1 * 40 + col) =
            make_float2(acc[nt][0] * SLAB_UNSCALE, acc[nt][1] * SLAB_UNSCALE);
        if (r2 < M) *(float2*)(C + (size_t)r2 * 40 + col) =
            make_float2(acc[nt][2] * SLAB_UNSCALE, acc[nt][3] * SLAB_UNSCALE);
    }
}

// ---------------------------------------------------------------------------
// Final: agg40 + b15 + log_softmax. Warp per node. fp32 gather, packed CSR.
// ---------------------------------------------------------------------------
__global__ void __launch_bounds__(256) spmm40_lsm_kernel(
    const float* __restrict__ accum, const float* __restrict__ b15,
    float* __restrict__ out, int n)
{
    GRID_SYNC();
    const int node = (blockIdx.x * blockDim.x + threadIdx.x) >> 5;
    if (node >= n) return;
    const int lane = threadIdx.x & 31;
    const int s = g_offs[node], e = g_offs[node + 1];

    float a1 = 0.f, a2 = 0.f;
    for (int i = s; i < e; i++) {
        int2 ew = g_csr[i];
        float w = __int_as_float(ew.y);
        const float* row = accum + (size_t)ew.x * 40;
        a1 = fmaf(w, row[lane], a1);
        if (lane < 8) a2 = fmaf(w, row[32 + lane], a2);
    }
    float v1 = a1 + b15[lane];
    float v2 = (lane < 8) ? (a2 + b15[32 + lane]) : -3.0e38f;

    float m = fmaxf(v1, v2);
#pragma unroll
    for (int o = 16; o > 0; o >>= 1) m = fmaxf(m, __shfl_xor_sync(0xffffffffu, m, o));
    float sum = expf(v1 - m) + ((lane < 8) ? expf(v2 - m) : 0.f);
#pragma unroll
    for (int o = 16; o > 0; o >>= 1) sum += __shfl_xor_sync(0xffffffffu, sum, o);
    float ls = m + logf(sum);

    out[(size_t)node * 40 + lane] = v1 - ls;
    if (lane < 8) out[(size_t)node * 40 + 32 + lane] = v2 - ls;
}

// ---------------------------------------------------------------------------
// Launch (all kernels via PDL: programmatic stream serialization)
// ---------------------------------------------------------------------------
template<typename F, typename... Args>
static void launch_pdl(F kernel, dim3 grid, dim3 block, size_t smem, Args... args)
{
    cudaLaunchConfig_t cfg = {};
    cfg.gridDim = grid;
    cfg.blockDim = block;
    cfg.dynamicSmemBytes = smem;
    cfg.stream = 0;
    cudaLaunchAttribute attr[1];
    attr[0].id = cudaLaunchAttributeProgrammaticStreamSerialization;
    attr[0].val.programmaticStreamSerializationAllowed = 1;
    cfg.attrs = attr;
    cfg.numAttrs = 1;
    cudaLaunchKernelEx(&cfg, kernel, args...);
}

extern "C" void kernel_launch(void* const* d_in, const int* in_sizes, int n_in,
                              void* d_out, int out_size)
{
    const float* x    = (const float*)d_in[0];
    const int*   esrc = (const int*)  d_in[1];
    const int*   edst = (const int*)  d_in[2];
    const float* ew   = (const float*)d_in[3];
    const float* W0   = (const float*)d_in[4];
    const float* b0   = (const float*)d_in[5];
    const float* W1   = (const float*)d_in[6];
    const float* b1   = (const float*)d_in[7];
    const float* Wmid = (const float*)d_in[8];
    const float* bmid = (const float*)d_in[9];
    const float* W15  = (const float*)d_in[10];
    const float* b15  = (const float*)d_in[11];

    const int E = in_sizes[1];
    const int n = in_sizes[0] / 256;
    float* out = (float*)d_out;

    float *z, *accum;
    __half *sup, *hf16, *wfh, *xf16;
    cudaGetSymbolAddress((void**)&z,     g_z);
    cudaGetSymbolAddress((void**)&sup,   g_sup);
    cudaGetSymbolAddress((void**)&accum, g_acc);
    cudaGetSymbolAddress((void**)&wfh,   g_wfh);
    cudaGetSymbolAddress((void**)&xf16,  g_xf16);
    cudaGetSymbolAddress((void**)&hf16,  g_hf16);

    cudaFuncSetAttribute(tgemmf_kernel<0>, cudaFuncAttributeMaxDynamicSharedMemorySize, SMEMSZ_GF);
    cudaFuncSetAttribute(tgemmf_kernel<1>, cudaFuncAttributeMaxDynamicSharedMemorySize, SMEMSZ_GF);
    cudaFuncSetAttribute(tgemm40f_kernel,  cudaFuncAttributeMaxDynamicSharedMemorySize, SMEMSZ_G40F);

    const int TB = 256;
    const int gridE = (E + TB - 1) / TB;
    const int gridN = (n + TB - 1) / TB;
    const int gridT = (n + 127) / 128;
    const int gridSpmm16 = (n + 15) / 16;
    const int gridSpmm32 = (n + 7) / 8;
    const size_t slab = (size_t)n * 128;

    // 1. CSR build + conversions
    launch_pdl(zero_deg_kernel, gridN, TB, 0, n);
    launch_pdl(hist_kernel, gridE, TB, 0, edst, E);
    launch_pdl(scan_kernel, 1, 1024, 0, n);
    launch_pdl(scatter_kernel, gridE, TB, 0, esrc, edst, ew, E);
    launch_pdl(cvt_w_kernel, (WT_TOTAL + TB - 1) / TB, TB, 0, W0, W1, Wmid, W15);
    launch_pdl(cvt_x_kernel, (n * 128 + TB - 1) / TB, TB, 0, x, n * 128);

    // 2. layer 1
    launch_pdl(tgemmf_kernel<0>, gridT, 256, SMEMSZ_GF,
               (const __half*)xf16, (const __half*)(wfh + WOFF_W0), b0, (void*)z, 0.f, n, 256);
    launch_pdl(tgemmf_kernel<1>, gridT, 256, SMEMSZ_GF,
               (const __half*)xf16, (const __half*)(wfh + WOFF_W1), (const float*)nullptr,
               (void*)sup, SUP_SCALE, n, 256);
    launch_pdl(spmm_relu_res_kernel<0>, gridSpmm16, 256, 0,
               (const __half*)sup, b1, (const float*)z, (const __half*)nullptr, hf16, n);

    // 3. mid layers
    for (int l = 0; l < 13; l++) {
        launch_pdl(tgemmf_kernel<1>, gridT, 256, SMEMSZ_GF,
                   (const __half*)(hf16 + (size_t)l * slab),
                   (const __half*)(wfh + WOFF_MID + (size_t)l * 16384),
                   (const float*)nullptr, (void*)sup, ACC2SUP, n, 128);
        launch_pdl(spmm_relu_res_kernel<1>, gridSpmm16, 256, 0,
                   (const __half*)sup, (const float*)(bmid + (size_t)l * 128),
                   (const float*)nullptr, (const __half*)(hf16 + (size_t)l * slab),
                   hf16 + (size_t)(l + 1) * slab, n);
    }

    // 4. P = X_cat @ W15
    launch_pdl(tgemm40f_kernel, gridT, 256, SMEMSZ_G40F,
               (const __half*)hf16, (const __half*)(wfh + WOFF_W15), accum, n);

    // 5. out = log_softmax(agg40(P) + b15)
    launch_pdl(spmm40_lsm_kernel, gridSpmm32, 256, 0,
               (const float*)accum, b15, out, n);
}